// round 11
// baseline (speedup 1.0000x reference)
#include <cuda_runtime.h>
#include <cuda_bf16.h>
#include <cstdint>

#define SEQ     4096
#define DMODEL  1024
#define DPROJ   4384
#define DINNER  2048
#define DCONVIN 2304
#define DSTATE  128
#define NH      32
#define HD      64
#define NCH     32
#define CH      128

// ---------------- scratch (static __device__, allocation-free) ----------------
__device__ float g_zx [SEQ * DPROJ];          // in_proj output [t][4384]
__device__ float g_xbc[SEQ * DCONVIN];        // conv+silu: x[0,2048) B[2048,2176) C[2176,2304)
__device__ float g_dt [NH * SEQ];             // softplus(dt), [h][t]
__device__ float g_L  [NH * SEQ];             // per-chunk inclusive cumsum of dt*A, [h][t]
__device__ float g_S  [NCH * NH * HD * DSTATE]; // chunk-local states
__device__ float g_Y  [SEQ * DINNER];         // ssm output
__device__ float g_Gram[NCH * CH * CH];       // per-chunk C.B^T gram (head-independent)
__device__ float g_Inter[NCH * CH * DINNER];  // per-chunk inter-term C @ Hcat^T

// pre-converted bf16 operands (packed bf16x2 in uint32)
__device__ uint32_t g_u16[SEQ * DMODEL / 2];
__device__ uint32_t g_Whi[DPROJ * DMODEL / 2];
__device__ uint32_t g_Wlo[DPROJ * DMODEL / 2];
__device__ uint32_t g_Vhi[DMODEL * DINNER / 2];
__device__ uint32_t g_Vlo[DMODEL * DINNER / 2];
__device__ uint32_t g_Ghi[SEQ * DINNER / 2];
__device__ uint32_t g_Glo[SEQ * DINNER / 2];
__device__ uint32_t g_Hhi[NCH * DINNER * DSTATE / 2];  // chunk-initial states, split bf16
__device__ uint32_t g_Hlo[NCH * DINNER * DSTATE / 2];
__device__ uint32_t g_Chi[SEQ * DSTATE / 2];           // C block split
__device__ uint32_t g_Clo[SEQ * DSTATE / 2];

__device__ __forceinline__ float bf16r(float x) {
    return __bfloat162float(__float2bfloat16(x));
}
__device__ __forceinline__ uint32_t packbf2(float x, float y) {
    __nv_bfloat162 t = __floats2bfloat162_rn(x, y);
    return *(uint32_t*)&t;
}
__device__ __forceinline__ void cp16(void* sdst, const void* gsrc, int sz) {
    uint32_t sa = (uint32_t)__cvta_generic_to_shared(sdst);
    asm volatile("cp.async.cg.shared.global [%0], [%1], 16, %2;" :: "r"(sa), "l"(gsrc), "r"(sz));
}
__device__ __forceinline__ void ldsm4(uint32_t& r0, uint32_t& r1, uint32_t& r2, uint32_t& r3,
                                      uint32_t saddr) {
    asm volatile("ldmatrix.sync.aligned.m8n8.x4.shared.b16 {%0,%1,%2,%3}, [%4];"
                 : "=r"(r0), "=r"(r1), "=r"(r2), "=r"(r3) : "r"(saddr));
}
__device__ __forceinline__ void ldsm4t(uint32_t& r0, uint32_t& r1, uint32_t& r2, uint32_t& r3,
                                       uint32_t saddr) {
    asm volatile("ldmatrix.sync.aligned.m8n8.x4.trans.shared.b16 {%0,%1,%2,%3}, [%4];"
                 : "=r"(r0), "=r"(r1), "=r"(r2), "=r"(r3) : "r"(saddr));
}

#define MMA_BF16(d, a, b)                                                        \
    asm volatile("mma.sync.aligned.m16n8k16.row.col.f32.bf16.bf16.f32 "          \
                 "{%0,%1,%2,%3}, {%4,%5,%6,%7}, {%8,%9}, {%0,%1,%2,%3};"         \
                 : "+f"(d[0]), "+f"(d[1]), "+f"(d[2]), "+f"(d[3])                \
                 : "r"(a[0]), "r"(a[1]), "r"(a[2]), "r"(a[3]),                   \
                   "r"(b[0]), "r"(b[1]))

// ---------------- operand conversion kernels ----------------------------------
__global__ void convert_round_kernel(const float* __restrict__ src, uint32_t* __restrict__ dst, int npairs)
{
    int i = blockIdx.x * 256 + threadIdx.x;
    if (i >= npairs) return;
    float2 v = *(const float2*)(src + (size_t)i * 2);
    dst[i] = packbf2(v.x, v.y);
}
__global__ void convert_split_kernel(const float* __restrict__ src,
                                     uint32_t* __restrict__ hi, uint32_t* __restrict__ lo, int npairs)
{
    int i = blockIdx.x * 256 + threadIdx.x;
    if (i >= npairs) return;
    float2 v = *(const float2*)(src + (size_t)i * 2);
    float hx = bf16r(v.x), hy = bf16r(v.y);
    hi[i] = packbf2(hx, hy);
    lo[i] = packbf2(v.x - hx, v.y - hy);
}

// ---------------- tensor-core NT GEMM, cp.async pipeline + ldmatrix frags -----
template<int HAS_ALO, int CHUNKZ, int STAGES>
__global__ void __launch_bounds__(256) gemm_bf16s_kernel(
    const uint32_t* __restrict__ Ahi_g, const uint32_t* __restrict__ Alo_g,
    const uint32_t* __restrict__ Bhi_g, const uint32_t* __restrict__ Blo_g,
    float* __restrict__ C, int M, int N, int K)
{
    extern __shared__ uint32_t smem[];
    const uint32_t PS    = STAGES * 2560;
    const uint32_t ALS_O = PS;
    const uint32_t BHS_O = PS * (1 + (HAS_ALO ? 1 : 0));
    const uint32_t BLS_O = BHS_O + PS;
    uint32_t* Ahs = smem;
    uint32_t* Als = smem + ALS_O;
    uint32_t* Bhs = smem + BHS_O;
    uint32_t* Bls = smem + BLS_O;

    if (CHUNKZ) {
        size_t cz = blockIdx.z;
        Ahi_g += cz * (size_t)CH * (DSTATE / 2);
        if (HAS_ALO) Alo_g += cz * (size_t)CH * (DSTATE / 2);
        Bhi_g += cz * (size_t)DINNER * (DSTATE / 2);
        Blo_g += cz * (size_t)DINNER * (DSTATE / 2);
        C     += cz * (size_t)CH * DINNER;
    }

    const int K2 = K >> 1;
    const int KT = K2 >> 4;
    const int bn = blockIdx.x * 128;
    const int bm = blockIdx.y * 128;
    const int tid = threadIdx.x;
    const int lane = tid & 31;
    const int wid = tid >> 5;
    const int warpM = wid >> 2;
    const int warpN = wid & 3;
    const int g = lane >> 2;
    const int tig = lane & 3;

    const uint32_t sb32 = (uint32_t)__cvta_generic_to_shared(smem);
    const uint32_t AOFF = ((lane & 15) * 20 + (lane >> 4) * 4) * 4;
    const uint32_t BOFF = (((lane & 7) + (lane >> 4) * 8) * 20 + ((lane >> 3) & 1) * 4) * 4;

    auto issue = [&](int kt) {
        int k0 = kt * 16;
        int bo = (kt % STAGES) * 2560;
#pragma unroll
        for (int r = 0; r < 2; r++) {
            int qi = r * 256 + tid;
            int row = qi >> 2;
            int q4 = (qi & 3) * 4;
            size_t ga = (size_t)(bm + row) * K2 + k0 + q4;
            cp16(&Ahs[bo + row * 20 + q4], Ahi_g + ga, 16);
            if (HAS_ALO) cp16(&Als[bo + row * 20 + q4], Alo_g + ga, 16);
            int nn = bn + row;
            int sz = (nn < N) ? 16 : 0;
            size_t gb = (size_t)((nn < N) ? nn : 0) * K2 + k0 + q4;
            cp16(&Bhs[bo + row * 20 + q4], Bhi_g + gb, sz);
            cp16(&Bls[bo + row * 20 + q4], Blo_g + gb, sz);
        }
        asm volatile("cp.async.commit_group;" ::: "memory");
    };

    float acc[4][4][4];
#pragma unroll
    for (int mt = 0; mt < 4; mt++)
#pragma unroll
        for (int nt = 0; nt < 4; nt++)
#pragma unroll
            for (int e = 0; e < 4; e++) acc[mt][nt][e] = 0.f;

    auto compute = [&](int kt) {
        const uint32_t bo4 = (uint32_t)((kt % STAGES) * 2560) * 4;
#pragma unroll
        for (int kh = 0; kh < 2; kh++) {
            const uint32_t kb4 = (uint32_t)(kh * 8) * 4;
            uint32_t bhi[4][2], blo[4][2];
#pragma unroll
            for (int ntp = 0; ntp < 2; ntp++) {
                uint32_t nbase = sb32 + bo4 + (uint32_t)((warpN * 32 + ntp * 16) * 20) * 4 + kb4 + BOFF;
                ldsm4(bhi[ntp * 2][0], bhi[ntp * 2][1], bhi[ntp * 2 + 1][0], bhi[ntp * 2 + 1][1],
                      nbase + BHS_O * 4);
                ldsm4(blo[ntp * 2][0], blo[ntp * 2][1], blo[ntp * 2 + 1][0], blo[ntp * 2 + 1][1],
                      nbase + BLS_O * 4);
            }
#pragma unroll
            for (int mt = 0; mt < 4; mt++) {
                uint32_t abase = sb32 + bo4 + (uint32_t)((warpM * 64 + mt * 16) * 20) * 4 + kb4 + AOFF;
                uint32_t ah[4], al[4];
                ldsm4(ah[0], ah[1], ah[2], ah[3], abase);
                if (HAS_ALO) ldsm4(al[0], al[1], al[2], al[3], abase + ALS_O * 4);
#pragma unroll
                for (int nt = 0; nt < 4; nt++) MMA_BF16(acc[mt][nt], ah, bhi[nt]);
#pragma unroll
                for (int nt = 0; nt < 4; nt++) MMA_BF16(acc[mt][nt], ah, blo[nt]);
                if (HAS_ALO) {
#pragma unroll
                    for (int nt = 0; nt < 4; nt++) MMA_BF16(acc[mt][nt], al, bhi[nt]);
                }
            }
        }
    };

    if (STAGES == 3) {
        issue(0);
        issue(1);
        for (int kt = 0; kt < KT; kt++) {
            if (kt + 1 < KT) {
                asm volatile("cp.async.wait_group 1;" ::: "memory");
            } else {
                asm volatile("cp.async.wait_group 0;" ::: "memory");
            }
            __syncthreads();
            compute(kt);
            if (kt + 2 < KT) issue(kt + 2);
        }
    } else {
        issue(0);
        for (int kt = 0; kt < KT; kt++) {
            if (kt + 1 < KT) {
                issue(kt + 1);
                asm volatile("cp.async.wait_group 1;" ::: "memory");
            } else {
                asm volatile("cp.async.wait_group 0;" ::: "memory");
            }
            __syncthreads();
            compute(kt);
            __syncthreads();
        }
    }

#pragma unroll
    for (int mt = 0; mt < 4; mt++) {
        int row = bm + warpM * 64 + mt * 16 + g;
#pragma unroll
        for (int nt = 0; nt < 4; nt++) {
            int col = bn + warpN * 32 + nt * 8 + tig * 2;
            if (col < N) {
                C[(size_t)row * N + col]           = acc[mt][nt][0];
                C[(size_t)row * N + col + 1]       = acc[mt][nt][1];
                C[(size_t)(row + 8) * N + col]     = acc[mt][nt][2];
                C[(size_t)(row + 8) * N + col + 1] = acc[mt][nt][3];
            }
        }
    }
}

// ---------------- causal depthwise conv(4) + SiLU (8 timesteps/thread) --------
__global__ void conv_silu_kernel(const float* __restrict__ cw, const float* __restrict__ cb)
{
    int c = blockIdx.x * 256 + threadIdx.x;
    if (c >= DCONVIN) return;
    int t0 = blockIdx.y * 8;
    float w0 = cw[c * 4], w1 = cw[c * 4 + 1], w2 = cw[c * 4 + 2], w3 = cw[c * 4 + 3];
    float bias = cb[c];
    float v[11];
#pragma unroll
    for (int i = 0; i < 11; i++) {
        int tt = t0 - 3 + i;
        v[i] = (tt >= 0) ? g_zx[(size_t)tt * DPROJ + DINNER + c] : 0.f;
    }
#pragma unroll
    for (int i = 0; i < 8; i++) {
        float s = bias + v[i] * w0 + v[i + 1] * w1 + v[i + 2] * w2 + v[i + 3] * w3;
        g_xbc[(size_t)(t0 + i) * DCONVIN + c] = s / (1.f + expf(-s));
    }
}

// ---------------- softplus(dt)+dt_bias, dt*A, per-chunk inclusive cumsum ------
__global__ void dtscan_kernel(const float* __restrict__ dt_bias, const float* __restrict__ A_log)
{
    int bid = blockIdx.x;
    int c = bid >> 5, h = bid & 31;
    int s = threadIdx.x;
    int t = c * CH + s;
    float raw = g_zx[(size_t)t * DPROJ + (DINNER + DINNER + 2 * DSTATE) + h] + dt_bias[h];
    float dtv = (raw > 20.f) ? raw : log1pf(expf(raw));
    float Ah = -expf(A_log[h]);
    __shared__ float sm[CH];
    sm[s] = dtv * Ah;
    g_dt[h * SEQ + t] = dtv;
    __syncthreads();
    for (int off = 1; off < CH; off <<= 1) {
        float add = (s >= off) ? sm[s - off] : 0.f;
        __syncthreads();
        sm[s] += add;
        __syncthreads();
    }
    g_L[h * SEQ + t] = sm[s];
}

// ---------------- gram: G[c][s][j] = C_s . B_j (head-independent, NGROUPS=1) --
__global__ void __launch_bounds__(256) gram_kernel()
{
    int c = blockIdx.x;
    __shared__ float CsT[16 * 132];
    __shared__ float BsT[16 * 132];
    int tid = threadIdx.x;
    int ts = tid >> 4, tj = tid & 15;
    int base = c * CH;

    float acc[8][8];
#pragma unroll
    for (int i = 0; i < 8; i++)
#pragma unroll
        for (int k = 0; k < 8; k++) acc[i][k] = 0.f;

    for (int n0 = 0; n0 < DSTATE; n0 += 16) {
#pragma unroll
        for (int r = 0; r < 2; r++) {
            int qi = r * 256 + tid;
            int s = qi >> 2, nq = qi & 3;
            float4 vc = *(const float4*)&g_xbc[(size_t)(base + s) * DCONVIN + DINNER + DSTATE + n0 + nq * 4];
            CsT[(nq * 4 + 0) * 132 + s] = vc.x; CsT[(nq * 4 + 1) * 132 + s] = vc.y;
            CsT[(nq * 4 + 2) * 132 + s] = vc.z; CsT[(nq * 4 + 3) * 132 + s] = vc.w;
            float4 vb = *(const float4*)&g_xbc[(size_t)(base + s) * DCONVIN + DINNER + n0 + nq * 4];
            BsT[(nq * 4 + 0) * 132 + s] = vb.x; BsT[(nq * 4 + 1) * 132 + s] = vb.y;
            BsT[(nq * 4 + 2) * 132 + s] = vb.z; BsT[(nq * 4 + 3) * 132 + s] = vb.w;
        }
        __syncthreads();
#pragma unroll
        for (int nn = 0; nn < 16; nn++) {
            float4 c0 = *(float4*)&CsT[nn * 132 + ts * 8];
            float4 c1 = *(float4*)&CsT[nn * 132 + ts * 8 + 4];
            float4 b0 = *(float4*)&BsT[nn * 132 + tj * 8];
            float4 b1 = *(float4*)&BsT[nn * 132 + tj * 8 + 4];
            float cv[8] = {c0.x, c0.y, c0.z, c0.w, c1.x, c1.y, c1.z, c1.w};
            float bv[8] = {b0.x, b0.y, b0.z, b0.w, b1.x, b1.y, b1.z, b1.w};
#pragma unroll
            for (int i = 0; i < 8; i++)
#pragma unroll
                for (int k = 0; k < 8; k++) acc[i][k] += cv[i] * bv[k];
        }
        __syncthreads();
    }
#pragma unroll
    for (int i = 0; i < 8; i++) {
        size_t row = (size_t)(c * CH + ts * 8 + i) * CH;
        *(float4*)&g_Gram[row + tj * 8]     = make_float4(acc[i][0], acc[i][1], acc[i][2], acc[i][3]);
        *(float4*)&g_Gram[row + tj * 8 + 4] = make_float4(acc[i][4], acc[i][5], acc[i][6], acc[i][7]);
    }
}

// ---------------- split C block into bf16 hi/lo (for inter GEMM) --------------
__global__ void csplit_kernel()
{
    int i = blockIdx.x * 256 + threadIdx.x;   // over SEQ * 64 pairs
    if (i >= SEQ * (DSTATE / 2)) return;
    int t = i >> 6, n2 = (i & 63) * 2;
    float2 v = *(const float2*)&g_xbc[(size_t)t * DCONVIN + DINNER + DSTATE + n2];
    float h0 = bf16r(v.x), h1 = bf16r(v.y);
    g_Chi[(size_t)t * 64 + (n2 >> 1)] = packbf2(h0, h1);
    g_Clo[(size_t)t * 64 + (n2 >> 1)] = packbf2(v.x - h0, v.y - h1);
}

// ---------------- pass 1 (tensor cores): S[c,h] = (w.X)^T @ B -----------------
#define CS_AH 0
#define CS_AL (128 * 36)            // 4608
#define CS_BH (2 * 128 * 36)        // 9216
#define CS_BL (CS_BH + 128 * 68)    // 17920
#define CS_W  (CS_BL + 128 * 68)    // 26624
#define CS_SMEM_U32 (CS_W + 128)    // 26752 u32 = 107008 B
__global__ void __launch_bounds__(128) chunkstate_mma_kernel()
{
    extern __shared__ uint32_t cs[];
    float* ws = (float*)(cs + CS_W);
    int bid = blockIdx.x;
    int c = bid >> 5, h = bid & 31;
    int tid = threadIdx.x;
    int lane = tid & 31, wid = tid >> 5;
    int base = c * CH;

    {
        float Lend = g_L[h * SEQ + base + CH - 1];
        ws[tid] = __expf(Lend - g_L[h * SEQ + base + tid]) * g_dt[h * SEQ + base + tid];
    }
    __syncthreads();

    for (int idx = tid; idx < 128 * 16; idx += 128) {
        int j = idx >> 4, p4 = (idx & 15) * 4;
        float4 v = *(const float4*)&g_xbc[(size_t)(base + j) * DCONVIN + h * HD + p4];
        float w = ws[j];
        v.x *= w; v.y *= w; v.z *= w; v.w *= w;
        float hx = bf16r(v.x), hy = bf16r(v.y), hz = bf16r(v.z), hw = bf16r(v.w);
        int o = j * 36 + (p4 >> 1);
        cs[CS_AH + o]     = packbf2(hx, hy);
        cs[CS_AH + o + 1] = packbf2(hz, hw);
        cs[CS_AL + o]     = packbf2(v.x - hx, v.y - hy);
        cs[CS_AL + o + 1] = packbf2(v.z - hz, v.w - hw);
    }
    for (int idx = tid; idx < 128 * 32; idx += 128) {
        int j = idx >> 5, n4 = (idx & 31) * 4;
        float4 v = *(const float4*)&g_xbc[(size_t)(base + j) * DCONVIN + DINNER + n4];
        float hx = bf16r(v.x), hy = bf16r(v.y), hz = bf16r(v.z), hw = bf16r(v.w);
        int o = j * 68 + (n4 >> 1);
        cs[CS_BH + o]     = packbf2(hx, hy);
        cs[CS_BH + o + 1] = packbf2(hz, hw);
        cs[CS_BL + o]     = packbf2(v.x - hx, v.y - hy);
        cs[CS_BL + o + 1] = packbf2(v.z - hz, v.w - hw);
    }
    __syncthreads();

    uint32_t sb = (uint32_t)__cvta_generic_to_shared(cs);
    const uint32_t AOFFT = (((lane & 7) + (lane >> 4) * 8) * 36 + ((lane >> 3) & 1) * 4) * 4;
    const uint32_t BOFFT = (((lane & 7) + ((lane >> 3) & 1) * 8) * 68 + (lane >> 4) * 4) * 4;

    float acc[4][4][4];
#pragma unroll
    for (int mt = 0; mt < 4; mt++)
#pragma unroll
        for (int nt = 0; nt < 4; nt++)
#pragma unroll
            for (int e = 0; e < 4; e++) acc[mt][nt][e] = 0.f;

    for (int ks = 0; ks < 8; ks++) {
        uint32_t bh[4][2], bl[4][2];
#pragma unroll
        for (int np = 0; np < 2; np++) {
            uint32_t nbase = sb + (uint32_t)((ks * 16 * 68) * 4) + (uint32_t)((wid * 32 + np * 16) * 2) + BOFFT;
            ldsm4t(bh[np * 2][0], bh[np * 2][1], bh[np * 2 + 1][0], bh[np * 2 + 1][1],
                   nbase + CS_BH * 4);
            ldsm4t(bl[np * 2][0], bl[np * 2][1], bl[np * 2 + 1][0], bl[np * 2 + 1][1],
                   nbase + CS_BL * 4);
        }
#pragma unroll
        for (int mt = 0; mt < 4; mt++) {
            uint32_t abase = sb + (uint32_t)((ks * 16 * 36) * 4) + (uint32_t)((mt * 16) * 2) + AOFFT;
            uint32_t ah[4], al[4];
            ldsm4t(ah[0], ah[1], ah[2], ah[3], abase + CS_AH * 4);
            ldsm4t(al[0], al[1], al[2], al[3], abase + CS_AL * 4);
#pragma unroll
            for (int nt = 0; nt < 4; nt++) MMA_BF16(acc[mt][nt], ah, bh[nt]);
#pragma unroll
            for (int nt = 0; nt < 4; nt++) MMA_BF16(acc[mt][nt], ah, bl[nt]);
#pragma unroll
            for (int nt = 0; nt < 4; nt++) MMA_BF16(acc[mt][nt], al, bh[nt]);
        }
    }

    int g = lane >> 2, tig = lane & 3;
#pragma unroll
    for (int mt = 0; mt < 4; mt++) {
        int p = mt * 16 + g;
#pragma unroll
        for (int nt = 0; nt < 4; nt++) {
            int n = wid * 32 + nt * 8 + tig * 2;
            size_t row = ((size_t)(c * NH + h) * HD + p) * DSTATE;
            g_S[row + n]     = acc[mt][nt][0];
            g_S[row + n + 1] = acc[mt][nt][1];
            g_S[row + 8 * DSTATE + n]     = acc[mt][nt][2];
            g_S[row + 8 * DSTATE + n + 1] = acc[mt][nt][3];
        }
    }
}

// ---------------- pass 2: 32-step scan; emit H chunk-initial states as bf16 ---
__global__ void scan_kernel()
{
    int idx = blockIdx.x * 256 + threadIdx.x;   // 131072 threads, 2 n-values each
    int h = idx >> 12;
    int rem = idx & 4095;
    int p = rem >> 6;
    int n2 = (rem & 63) * 2;
    float h0 = 0.f, h1 = 0.f;
    for (int c = 0; c < NCH; c++) {
        size_t row = (size_t)c * DINNER + h * HD + p;
        float b0 = bf16r(h0), b1 = bf16r(h1);
        g_Hhi[row * 64 + (n2 >> 1)] = packbf2(b0, b1);
        g_Hlo[row * 64 + (n2 >> 1)] = packbf2(h0 - b0, h1 - b1);
        float2 s = *(const float2*)&g_S[((size_t)(c * NH + h) * HD + p) * DSTATE + n2];
        float dA = expf(g_L[h * SEQ + c * CH + CH - 1]);
        h0 = dA * h0 + s.x;
        h1 = dA * h1 + s.y;
    }
}

// ---------------- pass 3 (tensor cores): per-(chunk,head) output --------------
// Am[s][j] = mask * e^{Ls-Lj} dt_j * Gram[c][s][j]  (split bf16 in smem)
// Yintra = Am(128x128) @ X(128x64) via mma; fused: + e^{Ls}*Inter + D*x
#define CO_AMH 0
#define CO_AML (128 * 68)             // 8704
#define CO_XH  (2 * 128 * 68)         // 17408
#define CO_XL  (CO_XH + 128 * 36)     // 22016
#define CO_LS  (CO_XL + 128 * 36)     // 26624
#define CO_DTS (CO_LS + 128)          // 26752
#define CO_SMEM_U32 (CO_DTS + 128)    // 26880 u32 = 107520 B
__global__ void __launch_bounds__(128) chunkout_mma_kernel(const float* __restrict__ Dvec)
{
    extern __shared__ uint32_t cs[];
    float* Ls  = (float*)(cs + CO_LS);
    float* dts = (float*)(cs + CO_DTS);
    int bid = blockIdx.x;
    int c = bid >> 5, h = bid & 31;
    int tid = threadIdx.x;
    int lane = tid & 31, wid = tid >> 5;
    int base = c * CH;

    Ls[tid]  = g_L [h * SEQ + base + tid];
    dts[tid] = g_dt[h * SEQ + base + tid];
    __syncthreads();

    // stage 1: build Am split bf16 [s][j], stride 68 u32
    const float* Gc = g_Gram + (size_t)c * CH * CH;
    for (int idx = tid; idx < 128 * 64; idx += 128) {
        int s = idx >> 6;
        int j2 = (idx & 63) * 2;
        float2 gv = *(const float2*)&Gc[(size_t)s * CH + j2];
        float ls = Ls[s];
        float w0 = (j2 <= s)     ? __expf(ls - Ls[j2])     * dts[j2]     : 0.f;
        float w1 = (j2 + 1 <= s) ? __expf(ls - Ls[j2 + 1]) * dts[j2 + 1] : 0.f;
        float v0 = gv.x * w0, v1 = gv.y * w1;
        float h0 = bf16r(v0), h1 = bf16r(v1);
        int o = s * 68 + (j2 >> 1);
        cs[CO_AMH + o] = packbf2(h0, h1);
        cs[CO_AML + o] = packbf2(v0 - h0, v1 - h1);
    }
    // X tile [j][p], stride 36 u32 (k-major, same as chunkstate A layout)
    for (int idx = tid; idx < 128 * 16; idx += 128) {
        int j = idx >> 4, p4 = (idx & 15) * 4;
        float4 v = *(const float4*)&g_xbc[(size_t)(base + j) * DCONVIN + h * HD + p4];
        float hx = bf16r(v.x), hy = bf16r(v.y), hz = bf16r(v.z), hw = bf16r(v.w);
        int o = j * 36 + (p4 >> 1);
        cs[CO_XH + o]     = packbf2(hx, hy);
        cs[CO_XH + o + 1] = packbf2(hz, hw);
        cs[CO_XL + o]     = packbf2(v.x - hx, v.y - hy);
        cs[CO_XL + o + 1] = packbf2(v.z - hz, v.w - hw);
    }
    __syncthreads();

    uint32_t sb = (uint32_t)__cvta_generic_to_shared(cs);
    // A non-trans (row-major [s][j], stride 68)
    const uint32_t AOFF = ((lane & 15) * 68 + (lane >> 4) * 4) * 4;
    // B trans from [j][p], stride 36 (identical pattern to chunkstate A-trans)
    const uint32_t BOFFT = (((lane & 7) + ((lane >> 3) & 1) * 8) * 36 + (lane >> 4) * 4) * 4;

    float acc[8][2][4];
#pragma unroll
    for (int mt = 0; mt < 8; mt++)
#pragma unroll
        for (int nt = 0; nt < 2; nt++)
#pragma unroll
            for (int e = 0; e < 4; e++) acc[mt][nt][e] = 0.f;

    for (int ks = 0; ks < 8; ks++) {
        // B frags: warp's 16 p-columns at wid*16
        uint32_t bh[2][2], bl[2][2];
        uint32_t nbase = sb + (uint32_t)((ks * 16 * 36) * 4) + (uint32_t)((wid * 16) * 2) + BOFFT;
        ldsm4t(bh[0][0], bh[0][1], bh[1][0], bh[1][1], nbase + CO_XH * 4);
        ldsm4t(bl[0][0], bl[0][1], bl[1][0], bl[1][1], nbase + CO_XL * 4);
#pragma unroll
        for (int mt = 0; mt < 8; mt++) {
            uint32_t abase = sb + (uint32_t)((mt * 16 * 68) * 4) + (uint32_t)((ks * 8) * 4) + AOFF;
            uint32_t ah[4], al[4];
            ldsm4(ah[0], ah[1], ah[2], ah[3], abase + CO_AMH * 4);
            ldsm4(al[0], al[1], al[2], al[3], abase + CO_AML * 4);
#pragma unroll
            for (int nt = 0; nt < 2; nt++) MMA_BF16(acc[mt][nt], ah, bh[nt]);
#pragma unroll
            for (int nt = 0; nt < 2; nt++) MMA_BF16(acc[mt][nt], ah, bl[nt]);
#pragma unroll
            for (int nt = 0; nt < 2; nt++) MMA_BF16(acc[mt][nt], al, bh[nt]);
        }
    }

    int g = lane >> 2, tig = lane & 3;
    float Dh = Dvec[h];
#pragma unroll
    for (int mt = 0; mt < 8; mt++) {
        int s0 = mt * 16 + g;
        int s1 = s0 + 8;
        float es0 = expf(Ls[s0]);
        float es1 = expf(Ls[s1]);
#pragma unroll
        for (int nt = 0; nt < 2; nt++) {
            int p = wid * 16 + nt * 8 + tig * 2;
#pragma unroll
            for (int e = 0; e < 4; e++) {
                int s = (e < 2) ? s0 : s1;
                float es = (e < 2) ? es0 : es1;
                int pp = p + (e & 1);
                int trow = base + s;
                float xval = g_xbc[(size_t)trow * DCONVIN + h * HD + pp];
                float iv = g_Inter[((size_t)(c * CH + s)) * DINNER + h * HD + pp];
                g_Y[(size_t)trow * DINNER + h * HD + pp] = acc[mt][nt][e] + es * iv + Dh * xval;
            }
        }
    }
}

// ---------------- RMSNorm + SiLU gate -> split bf16 ---------------------------
__global__ void normgate_kernel(const float* __restrict__ nw, const float* __restrict__ nb)
{
    int t = blockIdx.x;
    int tid = threadIdx.x;
    __shared__ float red[256];
    float ss = 0.f;
    for (int d = tid; d < DINNER; d += 256) {
        float v = g_Y[(size_t)t * DINNER + d];
        ss += v * v;
    }
    red[tid] = ss;
    __syncthreads();
    for (int off = 128; off > 0; off >>= 1) {
        if (tid < off) red[tid] += red[tid + off];
        __syncthreads();
    }
    float inv = rsqrtf(red[0] / (float)DINNER + 1e-6f);
    for (int d = tid * 2; d < DINNER; d += 512) {
        float v0 = g_Y[(size_t)t * DINNER + d];
        float v1 = g_Y[(size_t)t * DINNER + d + 1];
        float g0 = v0 * inv * nw[d] + nb[d];
        float g1 = v1 * inv * nw[d + 1] + nb[d + 1];
        float z0 = g_zx[(size_t)t * DPROJ + d];
        float z1 = g_zx[(size_t)t * DPROJ + d + 1];
        g0 *= z0 / (1.f + expf(-z0));
        g1 *= z1 / (1.f + expf(-z1));
        float h0 = bf16r(g0), h1 = bf16r(g1);
        size_t pi = ((size_t)t * DINNER + d) >> 1;
        g_Ghi[pi] = packbf2(h0, h1);
        g_Glo[pi] = packbf2(g0 - h0, g1 - h1);
    }
}

// ---------------- launch ------------------------------------------------------
extern "C" void kernel_launch(void* const* d_in, const int* in_sizes, int n_in,
                              void* d_out, int out_size)
{
    const float* u       = (const float*)d_in[0];
    const float* W_in    = (const float*)d_in[1];
    const float* conv_w  = (const float*)d_in[2];
    const float* conv_b  = (const float*)d_in[3];
    const float* W_out   = (const float*)d_in[4];
    const float* norm_w  = (const float*)d_in[5];
    const float* norm_b  = (const float*)d_in[6];
    const float* dt_bias = (const float*)d_in[7];
    const float* A_log   = (const float*)d_in[8];
    const float* Dv      = (const float*)d_in[9];
    float* out = (float*)d_out;

    float *zx, *Inter;
    uint32_t *u16, *Whi, *Wlo, *Vhi, *Vlo, *Ghi, *Glo, *Hhi, *Hlo, *Chi, *Clo;
    cudaGetSymbolAddress((void**)&zx,   g_zx);
    cudaGetSymbolAddress((void**)&Inter,g_Inter);
    cudaGetSymbolAddress((void**)&u16,  g_u16);
    cudaGetSymbolAddress((void**)&Whi,  g_Whi);
    cudaGetSymbolAddress((void**)&Wlo,  g_Wlo);
    cudaGetSymbolAddress((void**)&Vhi,  g_Vhi);
    cudaGetSymbolAddress((void**)&Vlo,  g_Vlo);
    cudaGetSymbolAddress((void**)&Ghi,  g_Ghi);
    cudaGetSymbolAddress((void**)&Glo,  g_Glo);
    cudaGetSymbolAddress((void**)&Hhi,  g_Hhi);
    cudaGetSymbolAddress((void**)&Hlo,  g_Hlo);
    cudaGetSymbolAddress((void**)&Chi,  g_Chi);
    cudaGetSymbolAddress((void**)&Clo,  g_Clo);

    const int SM1 = 23040 * 4;   // gemm<0,0,3>
    const int SM2 = 20480 * 4;   // gemm<1,*,2>
    const int SMC = CS_SMEM_U32 * 4;
    const int SMO = CO_SMEM_U32 * 4;
    cudaFuncSetAttribute(gemm_bf16s_kernel<0, 0, 3>, cudaFuncAttributeMaxDynamicSharedMemorySize, SM1);
    cudaFuncSetAttribute(gemm_bf16s_kernel<1, 0, 2>, cudaFuncAttributeMaxDynamicSharedMemorySize, SM2);
    cudaFuncSetAttribute(gemm_bf16s_kernel<1, 1, 2>, cudaFuncAttributeMaxDynamicSharedMemorySize, SM2);
    cudaFuncSetAttribute(chunkstate_mma_kernel, cudaFuncAttributeMaxDynamicSharedMemorySize, SMC);
    cudaFuncSetAttribute(chunkout_mma_kernel, cudaFuncAttributeMaxDynamicSharedMemorySize, SMO);

    // 0. pre-convert operands
    {
        int np;
        np = SEQ * DMODEL / 2;
        convert_round_kernel<<<(np + 255) / 256, 256>>>(u, u16, np);
        np = DPROJ * DMODEL / 2;
        convert_split_kernel<<<(np + 255) / 256, 256>>>(W_in, Whi, Wlo, np);
        np = DMODEL * DINNER / 2;
        convert_split_kernel<<<(np + 255) / 256, 256>>>(W_out, Vhi, Vlo, np);
    }
    // 1. in_proj GEMM (3-stage single-sync pipeline, 2 mma)
    gemm_bf16s_kernel<0, 0, 3><<<dim3((DPROJ + 127) / 128, SEQ / 128), 256, SM1>>>(
        u16, nullptr, Whi, Wlo, zx, SEQ, DPROJ, DMODEL);
    // 2. causal depthwise conv + silu (8 t/thread)
    conv_silu_kernel<<<dim3((DCONVIN + 255) / 256, SEQ / 8), 256>>>(conv_w, conv_b);
    // 3. dt softplus + per-chunk cumsum
    dtscan_kernel<<<NCH * NH, CH>>>(dt_bias, A_log);
    // 3b. head-independent gram matrices
    gram_kernel<<<NCH, 256>>>();
    // 3c. split C block for inter GEMM
    csplit_kernel<<<(SEQ * (DSTATE / 2) + 255) / 256, 256>>>();
    // 4. chunk-local states (tensor cores)
    chunkstate_mma_kernel<<<NCH * NH, 128, SMC>>>();
    // 5. inter-chunk scan (emits split-bf16 H)
    scan_kernel<<<(NH * HD * (DSTATE / 2)) / 256, 256>>>();
    // 5b. inter term: per chunk, Inter[c] = C[c] @ Hcat[c]^T  (batched TC GEMM)
    gemm_bf16s_kernel<1, 1, 2><<<dim3(DINNER / 128, 1, NCH), 256, SM2>>>(
        Chi, Clo, Hhi, Hlo, Inter, CH, DINNER, DSTATE);
    // 6. per-chunk output (tensor cores: intra MMA + inter-combine + skip)
    chunkout_mma_kernel<<<NCH * NH, 128, SMO>>>(Dv);
    // 7. RMSNorm + gate -> split bf16
    normgate_kernel<<<SEQ, 256>>>(norm_w, norm_b);
    // 8. out_proj GEMM (2-stage, 3 mma)
    gemm_bf16s_kernel<1, 0, 2><<<dim3(DMODEL / 128, SEQ / 128), 256, SM2>>>(
        Ghi, Glo, Vhi, Vlo, out, SEQ, DMODEL, DINNER);
}

// round 12
// speedup vs baseline: 1.1167x; 1.1167x over previous
#include <cuda_runtime.h>
#include <cuda_bf16.h>
#include <cstdint>

#define SEQ     4096
#define DMODEL  1024
#define DPROJ   4384
#define DINNER  2048
#define DCONVIN 2304
#define DSTATE  128
#define NH      32
#define HD      64
#define NCH     32
#define CH      128

// ---------------- scratch (static __device__, allocation-free) ----------------
__device__ float g_zx [SEQ * DPROJ];          // in_proj output [t][4384]
__device__ float g_xbc[SEQ * DCONVIN];        // conv+silu: x[0,2048) B[2048,2176) C[2176,2304)
__device__ float g_dt [NH * SEQ];             // softplus(dt), [h][t]
__device__ float g_L  [NH * SEQ];             // per-chunk inclusive cumsum of dt*A, [h][t]
__device__ float g_S  [NCH * NH * HD * DSTATE]; // chunk-local states
__device__ float g_Y  [SEQ * DINNER];         // ssm output
__device__ float g_Gram[NCH * CH * CH];       // per-chunk C.B^T gram (head-independent)
__device__ float g_Inter[NCH * CH * DINNER];  // per-chunk inter-term C @ Hcat^T

// pre-converted bf16 operands (packed bf16x2 in uint32)
__device__ uint32_t g_u16[SEQ * DMODEL / 2];
__device__ uint32_t g_Whi[DPROJ * DMODEL / 2];
__device__ uint32_t g_Wlo[DPROJ * DMODEL / 2];
__device__ uint32_t g_Vhi[DMODEL * DINNER / 2];
__device__ uint32_t g_Vlo[DMODEL * DINNER / 2];
__device__ uint32_t g_Ghi[SEQ * DINNER / 2];
__device__ uint32_t g_Glo[SEQ * DINNER / 2];
__device__ uint32_t g_Hhi[NCH * DINNER * DSTATE / 2];  // chunk-initial states, split bf16
__device__ uint32_t g_Hlo[NCH * DINNER * DSTATE / 2];
__device__ uint32_t g_Chi[SEQ * DSTATE / 2];           // C block split
__device__ uint32_t g_Clo[SEQ * DSTATE / 2];

__device__ __forceinline__ float bf16r(float x) {
    return __bfloat162float(__float2bfloat16(x));
}
__device__ __forceinline__ uint32_t packbf2(float x, float y) {
    __nv_bfloat162 t = __floats2bfloat162_rn(x, y);
    return *(uint32_t*)&t;
}
__device__ __forceinline__ void cp16(void* sdst, const void* gsrc, int sz) {
    uint32_t sa = (uint32_t)__cvta_generic_to_shared(sdst);
    asm volatile("cp.async.cg.shared.global [%0], [%1], 16, %2;" :: "r"(sa), "l"(gsrc), "r"(sz));
}
__device__ __forceinline__ void ldsm4(uint32_t& r0, uint32_t& r1, uint32_t& r2, uint32_t& r3,
                                      uint32_t saddr) {
    asm volatile("ldmatrix.sync.aligned.m8n8.x4.shared.b16 {%0,%1,%2,%3}, [%4];"
                 : "=r"(r0), "=r"(r1), "=r"(r2), "=r"(r3) : "r"(saddr));
}
__device__ __forceinline__ void ldsm4t(uint32_t& r0, uint32_t& r1, uint32_t& r2, uint32_t& r3,
                                       uint32_t saddr) {
    asm volatile("ldmatrix.sync.aligned.m8n8.x4.trans.shared.b16 {%0,%1,%2,%3}, [%4];"
                 : "=r"(r0), "=r"(r1), "=r"(r2), "=r"(r3) : "r"(saddr));
}

#define MMA_BF16(d, a, b)                                                        \
    asm volatile("mma.sync.aligned.m16n8k16.row.col.f32.bf16.bf16.f32 "          \
                 "{%0,%1,%2,%3}, {%4,%5,%6,%7}, {%8,%9}, {%0,%1,%2,%3};"         \
                 : "+f"(d[0]), "+f"(d[1]), "+f"(d[2]), "+f"(d[3])                \
                 : "r"(a[0]), "r"(a[1]), "r"(a[2]), "r"(a[3]),                   \
                   "r"(b[0]), "r"(b[1]))

// ---------------- operand conversion kernels ----------------------------------
__global__ void convert_round_kernel(const float* __restrict__ src, uint32_t* __restrict__ dst, int npairs)
{
    int i = blockIdx.x * 256 + threadIdx.x;
    if (i >= npairs) return;
    float2 v = *(const float2*)(src + (size_t)i * 2);
    dst[i] = packbf2(v.x, v.y);
}
__global__ void convert_split_kernel(const float* __restrict__ src,
                                     uint32_t* __restrict__ hi, uint32_t* __restrict__ lo, int npairs)
{
    int i = blockIdx.x * 256 + threadIdx.x;
    if (i >= npairs) return;
    float2 v = *(const float2*)(src + (size_t)i * 2);
    float hx = bf16r(v.x), hy = bf16r(v.y);
    hi[i] = packbf2(hx, hy);
    lo[i] = packbf2(v.x - hx, v.y - hy);
}

// ---------------- tensor-core NT GEMM, cp.async pipeline + ldmatrix frags -----
template<int HAS_ALO, int CHUNKZ, int STAGES>
__global__ void __launch_bounds__(256) gemm_bf16s_kernel(
    const uint32_t* __restrict__ Ahi_g, const uint32_t* __restrict__ Alo_g,
    const uint32_t* __restrict__ Bhi_g, const uint32_t* __restrict__ Blo_g,
    float* __restrict__ C, int M, int N, int K)
{
    extern __shared__ uint32_t smem[];
    const uint32_t PS    = STAGES * 2560;
    const uint32_t ALS_O = PS;
    const uint32_t BHS_O = PS * (1 + (HAS_ALO ? 1 : 0));
    const uint32_t BLS_O = BHS_O + PS;
    uint32_t* Ahs = smem;
    uint32_t* Als = smem + ALS_O;
    uint32_t* Bhs = smem + BHS_O;
    uint32_t* Bls = smem + BLS_O;

    if (CHUNKZ) {
        size_t cz = blockIdx.z;
        Ahi_g += cz * (size_t)CH * (DSTATE / 2);
        if (HAS_ALO) Alo_g += cz * (size_t)CH * (DSTATE / 2);
        Bhi_g += cz * (size_t)DINNER * (DSTATE / 2);
        Blo_g += cz * (size_t)DINNER * (DSTATE / 2);
        C     += cz * (size_t)CH * DINNER;
    }

    const int K2 = K >> 1;
    const int KT = K2 >> 4;
    const int bn = blockIdx.x * 128;
    const int bm = blockIdx.y * 128;
    const int tid = threadIdx.x;
    const int lane = tid & 31;
    const int wid = tid >> 5;
    const int warpM = wid >> 2;
    const int warpN = wid & 3;
    const int g = lane >> 2;
    const int tig = lane & 3;

    const uint32_t sb32 = (uint32_t)__cvta_generic_to_shared(smem);
    const uint32_t AOFF = ((lane & 15) * 20 + (lane >> 4) * 4) * 4;
    const uint32_t BOFF = (((lane & 7) + (lane >> 4) * 8) * 20 + ((lane >> 3) & 1) * 4) * 4;

    auto issue = [&](int kt) {
        int k0 = kt * 16;
        int bo = (kt % STAGES) * 2560;
#pragma unroll
        for (int r = 0; r < 2; r++) {
            int qi = r * 256 + tid;
            int row = qi >> 2;
            int q4 = (qi & 3) * 4;
            size_t ga = (size_t)(bm + row) * K2 + k0 + q4;
            cp16(&Ahs[bo + row * 20 + q4], Ahi_g + ga, 16);
            if (HAS_ALO) cp16(&Als[bo + row * 20 + q4], Alo_g + ga, 16);
            int nn = bn + row;
            int sz = (nn < N) ? 16 : 0;
            size_t gb = (size_t)((nn < N) ? nn : 0) * K2 + k0 + q4;
            cp16(&Bhs[bo + row * 20 + q4], Bhi_g + gb, sz);
            cp16(&Bls[bo + row * 20 + q4], Blo_g + gb, sz);
        }
        asm volatile("cp.async.commit_group;" ::: "memory");
    };

    float acc[4][4][4];
#pragma unroll
    for (int mt = 0; mt < 4; mt++)
#pragma unroll
        for (int nt = 0; nt < 4; nt++)
#pragma unroll
            for (int e = 0; e < 4; e++) acc[mt][nt][e] = 0.f;

    auto compute = [&](int kt) {
        const uint32_t bo4 = (uint32_t)((kt % STAGES) * 2560) * 4;
#pragma unroll
        for (int kh = 0; kh < 2; kh++) {
            const uint32_t kb4 = (uint32_t)(kh * 8) * 4;
            uint32_t bhi[4][2], blo[4][2];
#pragma unroll
            for (int ntp = 0; ntp < 2; ntp++) {
                uint32_t nbase = sb32 + bo4 + (uint32_t)((warpN * 32 + ntp * 16) * 20) * 4 + kb4 + BOFF;
                ldsm4(bhi[ntp * 2][0], bhi[ntp * 2][1], bhi[ntp * 2 + 1][0], bhi[ntp * 2 + 1][1],
                      nbase + BHS_O * 4);
                ldsm4(blo[ntp * 2][0], blo[ntp * 2][1], blo[ntp * 2 + 1][0], blo[ntp * 2 + 1][1],
                      nbase + BLS_O * 4);
            }
#pragma unroll
            for (int mt = 0; mt < 4; mt++) {
                uint32_t abase = sb32 + bo4 + (uint32_t)((warpM * 64 + mt * 16) * 20) * 4 + kb4 + AOFF;
                uint32_t ah[4], al[4];
                ldsm4(ah[0], ah[1], ah[2], ah[3], abase);
                if (HAS_ALO) ldsm4(al[0], al[1], al[2], al[3], abase + ALS_O * 4);
#pragma unroll
                for (int nt = 0; nt < 4; nt++) MMA_BF16(acc[mt][nt], ah, bhi[nt]);
#pragma unroll
                for (int nt = 0; nt < 4; nt++) MMA_BF16(acc[mt][nt], ah, blo[nt]);
                if (HAS_ALO) {
#pragma unroll
                    for (int nt = 0; nt < 4; nt++) MMA_BF16(acc[mt][nt], al, bhi[nt]);
                }
            }
        }
    };

    if (STAGES == 3) {
        issue(0);
        issue(1);
        for (int kt = 0; kt < KT; kt++) {
            if (kt + 1 < KT) {
                asm volatile("cp.async.wait_group 1;" ::: "memory");
            } else {
                asm volatile("cp.async.wait_group 0;" ::: "memory");
            }
            __syncthreads();
            compute(kt);
            if (kt + 2 < KT) issue(kt + 2);
        }
    } else {
        issue(0);
        for (int kt = 0; kt < KT; kt++) {
            if (kt + 1 < KT) {
                issue(kt + 1);
                asm volatile("cp.async.wait_group 1;" ::: "memory");
            } else {
                asm volatile("cp.async.wait_group 0;" ::: "memory");
            }
            __syncthreads();
            compute(kt);
            __syncthreads();
        }
    }

#pragma unroll
    for (int mt = 0; mt < 4; mt++) {
        int row = bm + warpM * 64 + mt * 16 + g;
#pragma unroll
        for (int nt = 0; nt < 4; nt++) {
            int col = bn + warpN * 32 + nt * 8 + tig * 2;
            if (col < N) {
                C[(size_t)row * N + col]           = acc[mt][nt][0];
                C[(size_t)row * N + col + 1]       = acc[mt][nt][1];
                C[(size_t)(row + 8) * N + col]     = acc[mt][nt][2];
                C[(size_t)(row + 8) * N + col + 1] = acc[mt][nt][3];
            }
        }
    }
}

// ---------------- causal depthwise conv(4) + SiLU (8 timesteps/thread) --------
__global__ void conv_silu_kernel(const float* __restrict__ cw, const float* __restrict__ cb)
{
    int c = blockIdx.x * 256 + threadIdx.x;
    if (c >= DCONVIN) return;
    int t0 = blockIdx.y * 8;
    float w0 = cw[c * 4], w1 = cw[c * 4 + 1], w2 = cw[c * 4 + 2], w3 = cw[c * 4 + 3];
    float bias = cb[c];
    float v[11];
#pragma unroll
    for (int i = 0; i < 11; i++) {
        int tt = t0 - 3 + i;
        v[i] = (tt >= 0) ? g_zx[(size_t)tt * DPROJ + DINNER + c] : 0.f;
    }
#pragma unroll
    for (int i = 0; i < 8; i++) {
        float s = bias + v[i] * w0 + v[i + 1] * w1 + v[i + 2] * w2 + v[i + 3] * w3;
        g_xbc[(size_t)(t0 + i) * DCONVIN + c] = s / (1.f + expf(-s));
    }
}

// ---------------- softplus(dt)+dt_bias, dt*A, per-chunk inclusive cumsum ------
__global__ void dtscan_kernel(const float* __restrict__ dt_bias, const float* __restrict__ A_log)
{
    int bid = blockIdx.x;
    int c = bid >> 5, h = bid & 31;
    int s = threadIdx.x;
    int t = c * CH + s;
    float raw = g_zx[(size_t)t * DPROJ + (DINNER + DINNER + 2 * DSTATE) + h] + dt_bias[h];
    float dtv = (raw > 20.f) ? raw : log1pf(expf(raw));
    float Ah = -expf(A_log[h]);
    __shared__ float sm[CH];
    sm[s] = dtv * Ah;
    g_dt[h * SEQ + t] = dtv;
    __syncthreads();
    for (int off = 1; off < CH; off <<= 1) {
        float add = (s >= off) ? sm[s - off] : 0.f;
        __syncthreads();
        sm[s] += add;
        __syncthreads();
    }
    g_L[h * SEQ + t] = sm[s];
}

// ---------------- gram: G[c][s][j] = C_s . B_j (head-independent, NGROUPS=1) --
__global__ void __launch_bounds__(256) gram_kernel()
{
    int c = blockIdx.x;
    __shared__ float CsT[16 * 132];
    __shared__ float BsT[16 * 132];
    int tid = threadIdx.x;
    int ts = tid >> 4, tj = tid & 15;
    int base = c * CH;

    float acc[8][8];
#pragma unroll
    for (int i = 0; i < 8; i++)
#pragma unroll
        for (int k = 0; k < 8; k++) acc[i][k] = 0.f;

    for (int n0 = 0; n0 < DSTATE; n0 += 16) {
#pragma unroll
        for (int r = 0; r < 2; r++) {
            int qi = r * 256 + tid;
            int s = qi >> 2, nq = qi & 3;
            float4 vc = *(const float4*)&g_xbc[(size_t)(base + s) * DCONVIN + DINNER + DSTATE + n0 + nq * 4];
            CsT[(nq * 4 + 0) * 132 + s] = vc.x; CsT[(nq * 4 + 1) * 132 + s] = vc.y;
            CsT[(nq * 4 + 2) * 132 + s] = vc.z; CsT[(nq * 4 + 3) * 132 + s] = vc.w;
            float4 vb = *(const float4*)&g_xbc[(size_t)(base + s) * DCONVIN + DINNER + n0 + nq * 4];
            BsT[(nq * 4 + 0) * 132 + s] = vb.x; BsT[(nq * 4 + 1) * 132 + s] = vb.y;
            BsT[(nq * 4 + 2) * 132 + s] = vb.z; BsT[(nq * 4 + 3) * 132 + s] = vb.w;
        }
        __syncthreads();
#pragma unroll
        for (int nn = 0; nn < 16; nn++) {
            float4 c0 = *(float4*)&CsT[nn * 132 + ts * 8];
            float4 c1 = *(float4*)&CsT[nn * 132 + ts * 8 + 4];
            float4 b0 = *(float4*)&BsT[nn * 132 + tj * 8];
            float4 b1 = *(float4*)&BsT[nn * 132 + tj * 8 + 4];
            float cv[8] = {c0.x, c0.y, c0.z, c0.w, c1.x, c1.y, c1.z, c1.w};
            float bv[8] = {b0.x, b0.y, b0.z, b0.w, b1.x, b1.y, b1.z, b1.w};
#pragma unroll
            for (int i = 0; i < 8; i++)
#pragma unroll
                for (int k = 0; k < 8; k++) acc[i][k] += cv[i] * bv[k];
        }
        __syncthreads();
    }
#pragma unroll
    for (int i = 0; i < 8; i++) {
        size_t row = (size_t)(c * CH + ts * 8 + i) * CH;
        *(float4*)&g_Gram[row + tj * 8]     = make_float4(acc[i][0], acc[i][1], acc[i][2], acc[i][3]);
        *(float4*)&g_Gram[row + tj * 8 + 4] = make_float4(acc[i][4], acc[i][5], acc[i][6], acc[i][7]);
    }
}

// ---------------- split C block into bf16 hi/lo (for inter GEMM) --------------
__global__ void csplit_kernel()
{
    int i = blockIdx.x * 256 + threadIdx.x;   // over SEQ * 64 pairs
    if (i >= SEQ * (DSTATE / 2)) return;
    int t = i >> 6, n2 = (i & 63) * 2;
    float2 v = *(const float2*)&g_xbc[(size_t)t * DCONVIN + DINNER + DSTATE + n2];
    float h0 = bf16r(v.x), h1 = bf16r(v.y);
    g_Chi[(size_t)t * 64 + (n2 >> 1)] = packbf2(h0, h1);
    g_Clo[(size_t)t * 64 + (n2 >> 1)] = packbf2(v.x - h0, v.y - h1);
}

// ---------------- pass 1 (tensor cores): S[c,h] = (w.X)^T @ B -----------------
#define CS_AH 0
#define CS_AL (128 * 36)            // 4608
#define CS_BH (2 * 128 * 36)        // 9216
#define CS_BL (CS_BH + 128 * 68)    // 17920
#define CS_W  (CS_BL + 128 * 68)    // 26624
#define CS_SMEM_U32 (CS_W + 128)    // 26752 u32 = 107008 B
__global__ void __launch_bounds__(128) chunkstate_mma_kernel()
{
    extern __shared__ uint32_t cs[];
    float* ws = (float*)(cs + CS_W);
    int bid = blockIdx.x;
    int c = bid >> 5, h = bid & 31;
    int tid = threadIdx.x;
    int lane = tid & 31, wid = tid >> 5;
    int base = c * CH;

    {
        float Lend = g_L[h * SEQ + base + CH - 1];
        ws[tid] = __expf(Lend - g_L[h * SEQ + base + tid]) * g_dt[h * SEQ + base + tid];
    }
    __syncthreads();

    for (int idx = tid; idx < 128 * 16; idx += 128) {
        int j = idx >> 4, p4 = (idx & 15) * 4;
        float4 v = *(const float4*)&g_xbc[(size_t)(base + j) * DCONVIN + h * HD + p4];
        float w = ws[j];
        v.x *= w; v.y *= w; v.z *= w; v.w *= w;
        float hx = bf16r(v.x), hy = bf16r(v.y), hz = bf16r(v.z), hw = bf16r(v.w);
        int o = j * 36 + (p4 >> 1);
        cs[CS_AH + o]     = packbf2(hx, hy);
        cs[CS_AH + o + 1] = packbf2(hz, hw);
        cs[CS_AL + o]     = packbf2(v.x - hx, v.y - hy);
        cs[CS_AL + o + 1] = packbf2(v.z - hz, v.w - hw);
    }
    for (int idx = tid; idx < 128 * 32; idx += 128) {
        int j = idx >> 5, n4 = (idx & 31) * 4;
        float4 v = *(const float4*)&g_xbc[(size_t)(base + j) * DCONVIN + DINNER + n4];
        float hx = bf16r(v.x), hy = bf16r(v.y), hz = bf16r(v.z), hw = bf16r(v.w);
        int o = j * 68 + (n4 >> 1);
        cs[CS_BH + o]     = packbf2(hx, hy);
        cs[CS_BH + o + 1] = packbf2(hz, hw);
        cs[CS_BL + o]     = packbf2(v.x - hx, v.y - hy);
        cs[CS_BL + o + 1] = packbf2(v.z - hz, v.w - hw);
    }
    __syncthreads();

    uint32_t sb = (uint32_t)__cvta_generic_to_shared(cs);
    const uint32_t AOFFT = (((lane & 7) + (lane >> 4) * 8) * 36 + ((lane >> 3) & 1) * 4) * 4;
    const uint32_t BOFFT = (((lane & 7) + ((lane >> 3) & 1) * 8) * 68 + (lane >> 4) * 4) * 4;

    float acc[4][4][4];
#pragma unroll
    for (int mt = 0; mt < 4; mt++)
#pragma unroll
        for (int nt = 0; nt < 4; nt++)
#pragma unroll
            for (int e = 0; e < 4; e++) acc[mt][nt][e] = 0.f;

    for (int ks = 0; ks < 8; ks++) {
        uint32_t bh[4][2], bl[4][2];
#pragma unroll
        for (int np = 0; np < 2; np++) {
            uint32_t nbase = sb + (uint32_t)((ks * 16 * 68) * 4) + (uint32_t)((wid * 32 + np * 16) * 2) + BOFFT;
            ldsm4t(bh[np * 2][0], bh[np * 2][1], bh[np * 2 + 1][0], bh[np * 2 + 1][1],
                   nbase + CS_BH * 4);
            ldsm4t(bl[np * 2][0], bl[np * 2][1], bl[np * 2 + 1][0], bl[np * 2 + 1][1],
                   nbase + CS_BL * 4);
        }
#pragma unroll
        for (int mt = 0; mt < 4; mt++) {
            uint32_t abase = sb + (uint32_t)((ks * 16 * 36) * 4) + (uint32_t)((mt * 16) * 2) + AOFFT;
            uint32_t ah[4], al[4];
            ldsm4t(ah[0], ah[1], ah[2], ah[3], abase + CS_AH * 4);
            ldsm4t(al[0], al[1], al[2], al[3], abase + CS_AL * 4);
#pragma unroll
            for (int nt = 0; nt < 4; nt++) MMA_BF16(acc[mt][nt], ah, bh[nt]);
#pragma unroll
            for (int nt = 0; nt < 4; nt++) MMA_BF16(acc[mt][nt], ah, bl[nt]);
#pragma unroll
            for (int nt = 0; nt < 4; nt++) MMA_BF16(acc[mt][nt], al, bh[nt]);
        }
    }

    int g = lane >> 2, tig = lane & 3;
#pragma unroll
    for (int mt = 0; mt < 4; mt++) {
        int p = mt * 16 + g;
#pragma unroll
        for (int nt = 0; nt < 4; nt++) {
            int n = wid * 32 + nt * 8 + tig * 2;
            size_t row = ((size_t)(c * NH + h) * HD + p) * DSTATE;
            g_S[row + n]     = acc[mt][nt][0];
            g_S[row + n + 1] = acc[mt][nt][1];
            g_S[row + 8 * DSTATE + n]     = acc[mt][nt][2];
            g_S[row + 8 * DSTATE + n + 1] = acc[mt][nt][3];
        }
    }
}

// ---------------- pass 2: 32-step scan; emit H chunk-initial states as bf16 ---
__global__ void scan_kernel()
{
    int idx = blockIdx.x * 256 + threadIdx.x;   // 131072 threads, 2 n-values each
    int h = idx >> 12;
    int rem = idx & 4095;
    int p = rem >> 6;
    int n2 = (rem & 63) * 2;
    float h0 = 0.f, h1 = 0.f;
    for (int c = 0; c < NCH; c++) {
        size_t row = (size_t)c * DINNER + h * HD + p;
        float b0 = bf16r(h0), b1 = bf16r(h1);
        g_Hhi[row * 64 + (n2 >> 1)] = packbf2(b0, b1);
        g_Hlo[row * 64 + (n2 >> 1)] = packbf2(h0 - b0, h1 - b1);
        float2 s = *(const float2*)&g_S[((size_t)(c * NH + h) * HD + p) * DSTATE + n2];
        float dA = expf(g_L[h * SEQ + c * CH + CH - 1]);
        h0 = dA * h0 + s.x;
        h1 = dA * h1 + s.y;
    }
}

// ---------------- pass 3 (tensor cores): per-(chunk,head) output --------------
// Am[s][j] = mask * e^{Ls-Lj} dt_j * Gram[c][s][j]  (split bf16 in smem)
// Yintra = Am(128x128) @ X(128x64) via mma (warps 0-3); accum staged to smem;
// coalesced epilogue (all 8 warps): + e^{Ls}*Inter + D*x -> g_Y
#define CO_AMH 0
#define CO_AML (128 * 68)             // 8704
#define CO_XH  (2 * 128 * 68)         // 17408
#define CO_XL  (CO_XH + 128 * 36)     // 22016
#define CO_LS  (CO_XL + 128 * 36)     // 26624
#define CO_DTS (CO_LS + 128)          // 26752
#define CO_SMEM_U32 (CO_DTS + 128)    // 26880 u32 = 107520 B
__global__ void __launch_bounds__(256) chunkout_mma_kernel(const float* __restrict__ Dvec)
{
    extern __shared__ uint32_t cs[];
    float* Ls  = (float*)(cs + CO_LS);
    float* dts = (float*)(cs + CO_DTS);
    float* Yst = (float*)cs;            // reuses Am region post-MMA, stride 68
    int bid = blockIdx.x;
    int c = bid >> 5, h = bid & 31;
    int tid = threadIdx.x;
    int lane = tid & 31, wid = tid >> 5;
    int base = c * CH;

    if (tid < 128) {
        Ls[tid]  = g_L [h * SEQ + base + tid];
        dts[tid] = g_dt[h * SEQ + base + tid];
    }
    __syncthreads();

    // stage 1: build Am split bf16 [s][j], stride 68 u32 (all 256 threads)
    const float* Gc = g_Gram + (size_t)c * CH * CH;
    for (int idx = tid; idx < 128 * 64; idx += 256) {
        int s = idx >> 6;
        int j2 = (idx & 63) * 2;
        float2 gv = *(const float2*)&Gc[(size_t)s * CH + j2];
        float ls = Ls[s];
        float w0 = (j2 <= s)     ? __expf(ls - Ls[j2])     * dts[j2]     : 0.f;
        float w1 = (j2 + 1 <= s) ? __expf(ls - Ls[j2 + 1]) * dts[j2 + 1] : 0.f;
        float v0 = gv.x * w0, v1 = gv.y * w1;
        float h0 = bf16r(v0), h1 = bf16r(v1);
        int o = s * 68 + (j2 >> 1);
        cs[CO_AMH + o] = packbf2(h0, h1);
        cs[CO_AML + o] = packbf2(v0 - h0, v1 - h1);
    }
    // X tile [j][p], stride 36 u32 (k-major)
    for (int idx = tid; idx < 128 * 16; idx += 256) {
        int j = idx >> 4, p4 = (idx & 15) * 4;
        float4 v = *(const float4*)&g_xbc[(size_t)(base + j) * DCONVIN + h * HD + p4];
        float hx = bf16r(v.x), hy = bf16r(v.y), hz = bf16r(v.z), hw = bf16r(v.w);
        int o = j * 36 + (p4 >> 1);
        cs[CO_XH + o]     = packbf2(hx, hy);
        cs[CO_XH + o + 1] = packbf2(hz, hw);
        cs[CO_XL + o]     = packbf2(v.x - hx, v.y - hy);
        cs[CO_XL + o + 1] = packbf2(v.z - hz, v.w - hw);
    }
    __syncthreads();

    uint32_t sb = (uint32_t)__cvta_generic_to_shared(cs);
    const uint32_t AOFF = ((lane & 15) * 68 + (lane >> 4) * 4) * 4;
    const uint32_t BOFFT = (((lane & 7) + ((lane >> 3) & 1) * 8) * 36 + (lane >> 4) * 4) * 4;

    float acc[8][2][4];
    if (wid < 4) {
#pragma unroll
        for (int mt = 0; mt < 8; mt++)
#pragma unroll
            for (int nt = 0; nt < 2; nt++)
#pragma unroll
                for (int e = 0; e < 4; e++) acc[mt][nt][e] = 0.f;

        for (int ks = 0; ks < 8; ks++) {
            uint32_t bh[2][2], bl[2][2];
            uint32_t nbase = sb + (uint32_t)((ks * 16 * 36) * 4) + (uint32_t)((wid * 16) * 2) + BOFFT;
            ldsm4t(bh[0][0], bh[0][1], bh[1][0], bh[1][1], nbase + CO_XH * 4);
            ldsm4t(bl[0][0], bl[0][1], bl[1][0], bl[1][1], nbase + CO_XL * 4);
#pragma unroll
            for (int mt = 0; mt < 8; mt++) {
                uint32_t abase = sb + (uint32_t)((mt * 16 * 68) * 4) + (uint32_t)((ks * 8) * 4) + AOFF;
                uint32_t ah[4], al[4];
                ldsm4(ah[0], ah[1], ah[2], ah[3], abase + CO_AMH * 4);
                ldsm4(al[0], al[1], al[2], al[3], abase + CO_AML * 4);
#pragma unroll
                for (int nt = 0; nt < 2; nt++) MMA_BF16(acc[mt][nt], ah, bh[nt]);
#pragma unroll
                for (int nt = 0; nt < 2; nt++) MMA_BF16(acc[mt][nt], ah, bl[nt]);
#pragma unroll
                for (int nt = 0; nt < 2; nt++) MMA_BF16(acc[mt][nt], al, bh[nt]);
            }
        }
    }
    __syncthreads();   // all MMA reads of Am done before overwrite

    // stage accumulators into smem: Yst[s][p], stride 68 floats
    if (wid < 4) {
        int g = lane >> 2, tig = lane & 3;
#pragma unroll
        for (int mt = 0; mt < 8; mt++) {
            int s0 = mt * 16 + g;
#pragma unroll
            for (int nt = 0; nt < 2; nt++) {
                int p = wid * 16 + nt * 8 + tig * 2;
                *(float2*)&Yst[s0 * 68 + p]       = make_float2(acc[mt][nt][0], acc[mt][nt][1]);
                *(float2*)&Yst[(s0 + 8) * 68 + p] = make_float2(acc[mt][nt][2], acc[mt][nt][3]);
            }
        }
    }
    __syncthreads();

    // coalesced epilogue: 16 threads cover one row's 64 floats
    float Dh = Dvec[h];
    for (int idx = tid; idx < 128 * 16; idx += 256) {
        int s = idx >> 4, p4 = (idx & 15) * 4;
        int trow = base + s;
        float es = expf(Ls[s]);
        float4 yv = *(float4*)&Yst[s * 68 + p4];
        float4 xv = *(const float4*)&g_xbc[(size_t)trow * DCONVIN + h * HD + p4];
        float4 iv = *(const float4*)&g_Inter[((size_t)(c * CH + s)) * DINNER + h * HD + p4];
        float4 ov;
        ov.x = yv.x + es * iv.x + Dh * xv.x;
        ov.y = yv.y + es * iv.y + Dh * xv.y;
        ov.z = yv.z + es * iv.z + Dh * xv.z;
        ov.w = yv.w + es * iv.w + Dh * xv.w;
        *(float4*)&g_Y[(size_t)trow * DINNER + h * HD + p4] = ov;
    }
}

// ---------------- RMSNorm + SiLU gate -> split bf16 ---------------------------
__global__ void normgate_kernel(const float* __restrict__ nw, const float* __restrict__ nb)
{
    int t = blockIdx.x;
    int tid = threadIdx.x;
    __shared__ float red[256];
    float ss = 0.f;
    for (int d = tid; d < DINNER; d += 256) {
        float v = g_Y[(size_t)t * DINNER + d];
        ss += v * v;
    }
    red[tid] = ss;
    __syncthreads();
    for (int off = 128; off > 0; off >>= 1) {
        if (tid < off) red[tid] += red[tid + off];
        __syncthreads();
    }
    float inv = rsqrtf(red[0] / (float)DINNER + 1e-6f);
    for (int d = tid * 2; d < DINNER; d += 512) {
        float v0 = g_Y[(size_t)t * DINNER + d];
        float v1 = g_Y[(size_t)t * DINNER + d + 1];
        float g0 = v0 * inv * nw[d] + nb[d];
        float g1 = v1 * inv * nw[d + 1] + nb[d + 1];
        float z0 = g_zx[(size_t)t * DPROJ + d];
        float z1 = g_zx[(size_t)t * DPROJ + d + 1];
        g0 *= z0 / (1.f + expf(-z0));
        g1 *= z1 / (1.f + expf(-z1));
        float h0 = bf16r(g0), h1 = bf16r(g1);
        size_t pi = ((size_t)t * DINNER + d) >> 1;
        g_Ghi[pi] = packbf2(h0, h1);
        g_Glo[pi] = packbf2(g0 - h0, g1 - h1);
    }
}

// ---------------- launch ------------------------------------------------------
extern "C" void kernel_launch(void* const* d_in, const int* in_sizes, int n_in,
                              void* d_out, int out_size)
{
    const float* u       = (const float*)d_in[0];
    const float* W_in    = (const float*)d_in[1];
    const float* conv_w  = (const float*)d_in[2];
    const float* conv_b  = (const float*)d_in[3];
    const float* W_out   = (const float*)d_in[4];
    const float* norm_w  = (const float*)d_in[5];
    const float* norm_b  = (const float*)d_in[6];
    const float* dt_bias = (const float*)d_in[7];
    const float* A_log   = (const float*)d_in[8];
    const float* Dv      = (const float*)d_in[9];
    float* out = (float*)d_out;

    float *zx, *Inter;
    uint32_t *u16, *Whi, *Wlo, *Vhi, *Vlo, *Ghi, *Glo, *Hhi, *Hlo, *Chi, *Clo;
    cudaGetSymbolAddress((void**)&zx,   g_zx);
    cudaGetSymbolAddress((void**)&Inter,g_Inter);
    cudaGetSymbolAddress((void**)&u16,  g_u16);
    cudaGetSymbolAddress((void**)&Whi,  g_Whi);
    cudaGetSymbolAddress((void**)&Wlo,  g_Wlo);
    cudaGetSymbolAddress((void**)&Vhi,  g_Vhi);
    cudaGetSymbolAddress((void**)&Vlo,  g_Vlo);
    cudaGetSymbolAddress((void**)&Ghi,  g_Ghi);
    cudaGetSymbolAddress((void**)&Glo,  g_Glo);
    cudaGetSymbolAddress((void**)&Hhi,  g_Hhi);
    cudaGetSymbolAddress((void**)&Hlo,  g_Hlo);
    cudaGetSymbolAddress((void**)&Chi,  g_Chi);
    cudaGetSymbolAddress((void**)&Clo,  g_Clo);

    const int SM1 = 23040 * 4;   // gemm<0,0,3>
    const int SM2 = 20480 * 4;   // gemm<1,*,2>
    const int SMC = CS_SMEM_U32 * 4;
    const int SMO = CO_SMEM_U32 * 4;
    cudaFuncSetAttribute(gemm_bf16s_kernel<0, 0, 3>, cudaFuncAttributeMaxDynamicSharedMemorySize, SM1);
    cudaFuncSetAttribute(gemm_bf16s_kernel<1, 0, 2>, cudaFuncAttributeMaxDynamicSharedMemorySize, SM2);
    cudaFuncSetAttribute(gemm_bf16s_kernel<1, 1, 2>, cudaFuncAttributeMaxDynamicSharedMemorySize, SM2);
    cudaFuncSetAttribute(chunkstate_mma_kernel, cudaFuncAttributeMaxDynamicSharedMemorySize, SMC);
    cudaFuncSetAttribute(chunkout_mma_kernel, cudaFuncAttributeMaxDynamicSharedMemorySize, SMO);

    // 0. pre-convert operands
    {
        int np;
        np = SEQ * DMODEL / 2;
        convert_round_kernel<<<(np + 255) / 256, 256>>>(u, u16, np);
        np = DPROJ * DMODEL / 2;
        convert_split_kernel<<<(np + 255) / 256, 256>>>(W_in, Whi, Wlo, np);
        np = DMODEL * DINNER / 2;
        convert_split_kernel<<<(np + 255) / 256, 256>>>(W_out, Vhi, Vlo, np);
    }
    // 1. in_proj GEMM (3-stage single-sync pipeline, 2 mma)
    gemm_bf16s_kernel<0, 0, 3><<<dim3((DPROJ + 127) / 128, SEQ / 128), 256, SM1>>>(
        u16, nullptr, Whi, Wlo, zx, SEQ, DPROJ, DMODEL);
    // 2. causal depthwise conv + silu (8 t/thread)
    conv_silu_kernel<<<dim3((DCONVIN + 255) / 256, SEQ / 8), 256>>>(conv_w, conv_b);
    // 3. dt softplus + per-chunk cumsum
    dtscan_kernel<<<NCH * NH, CH>>>(dt_bias, A_log);
    // 3b. head-independent gram matrices
    gram_kernel<<<NCH, 256>>>();
    // 3c. split C block for inter GEMM
    csplit_kernel<<<(SEQ * (DSTATE / 2) + 255) / 256, 256>>>();
    // 4. chunk-local states (tensor cores)
    chunkstate_mma_kernel<<<NCH * NH, 128, SMC>>>();
    // 5. inter-chunk scan (emits split-bf16 H)
    scan_kernel<<<(NH * HD * (DSTATE / 2)) / 256, 256>>>();
    // 5b. inter term: per chunk, Inter[c] = C[c] @ Hcat[c]^T  (batched TC GEMM)
    gemm_bf16s_kernel<1, 1, 2><<<dim3(DINNER / 128, 1, NCH), 256, SM2>>>(
        Chi, Clo, Hhi, Hlo, Inter, CH, DINNER, DSTATE);
    // 6. per-chunk output (tensor cores + staged coalesced epilogue)
    chunkout_mma_kernel<<<NCH * NH, 256, SMO>>>(Dv);
    // 7. RMSNorm + gate -> split bf16
    normgate_kernel<<<SEQ, 256>>>(norm_w, norm_b);
    // 8. out_proj GEMM (2-stage, 3 mma)
    gemm_bf16s_kernel<1, 0, 2><<<dim3(DMODEL / 128, SEQ / 128), 256, SM2>>>(
        Ghi, Glo, Vhi, Vlo, out, SEQ, DMODEL, DINNER);
}

// round 14
// speedup vs baseline: 1.2373x; 1.1080x over previous
#include <cuda_runtime.h>
#include <cuda_bf16.h>
#include <cstdint>

#define SEQ     4096
#define DMODEL  1024
#define DPROJ   4384
#define DINNER  2048
#define DCONVIN 2304
#define DSTATE  128
#define NH      32
#define HD      64
#define NCH     32
#define CH      128

// ---------------- scratch (static __device__, allocation-free) ----------------
__device__ float g_zx [SEQ * DPROJ];
__device__ float g_xbc[SEQ * DCONVIN];
__device__ float g_dt [NH * SEQ];
__device__ float g_L  [NH * SEQ];
__device__ float g_S  [NCH * NH * HD * DSTATE];
__device__ float g_Y  [SEQ * DINNER];
__device__ float g_Gram[NCH * CH * CH];
__device__ float g_Inter[NCH * CH * DINNER];

__device__ uint32_t g_u16[SEQ * DMODEL / 2];
__device__ uint32_t g_Whi[DPROJ * DMODEL / 2];
__device__ uint32_t g_Wlo[DPROJ * DMODEL / 2];
__device__ uint32_t g_Vhi[DMODEL * DINNER / 2];
__device__ uint32_t g_Vlo[DMODEL * DINNER / 2];
__device__ uint32_t g_Ghi[SEQ * DINNER / 2];
__device__ uint32_t g_Glo[SEQ * DINNER / 2];
__device__ uint32_t g_Hhi[NCH * DINNER * DSTATE / 2];
__device__ uint32_t g_Hlo[NCH * DINNER * DSTATE / 2];
__device__ __nv_bfloat16 g_Chi16[SEQ * DSTATE];   // C block split, [t][128] bf16
__device__ __nv_bfloat16 g_Clo16[SEQ * DSTATE];

__device__ __forceinline__ float bf16r(float x) {
    return __bfloat162float(__float2bfloat16(x));
}
__device__ __forceinline__ uint32_t packbf2(float x, float y) {
    __nv_bfloat162 t = __floats2bfloat162_rn(x, y);
    return *(uint32_t*)&t;
}
__device__ __forceinline__ void cp16(void* sdst, const void* gsrc, int sz) {
    uint32_t sa = (uint32_t)__cvta_generic_to_shared(sdst);
    asm volatile("cp.async.cg.shared.global [%0], [%1], 16, %2;" :: "r"(sa), "l"(gsrc), "r"(sz));
}
__device__ __forceinline__ void ldsm4(uint32_t& r0, uint32_t& r1, uint32_t& r2, uint32_t& r3,
                                      uint32_t saddr) {
    asm volatile("ldmatrix.sync.aligned.m8n8.x4.shared.b16 {%0,%1,%2,%3}, [%4];"
                 : "=r"(r0), "=r"(r1), "=r"(r2), "=r"(r3) : "r"(saddr));
}
__device__ __forceinline__ void ldsm4t(uint32_t& r0, uint32_t& r1, uint32_t& r2, uint32_t& r3,
                                       uint32_t saddr) {
    asm volatile("ldmatrix.sync.aligned.m8n8.x4.trans.shared.b16 {%0,%1,%2,%3}, [%4];"
                 : "=r"(r0), "=r"(r1), "=r"(r2), "=r"(r3) : "r"(saddr));
}

#define MMA_BF16(d, a, b)                                                        \
    asm volatile("mma.sync.aligned.m16n8k16.row.col.f32.bf16.bf16.f32 "          \
                 "{%0,%1,%2,%3}, {%4,%5,%6,%7}, {%8,%9}, {%0,%1,%2,%3};"         \
                 : "+f"(d[0]), "+f"(d[1]), "+f"(d[2]), "+f"(d[3])                \
                 : "r"(a[0]), "r"(a[1]), "r"(a[2]), "r"(a[3]),                   \
                   "r"(b[0]), "r"(b[1]))

// ---------------- operand conversion kernels ----------------------------------
__global__ void convert_round_kernel(const float* __restrict__ src, uint32_t* __restrict__ dst, int npairs)
{
    int i = blockIdx.x * 256 + threadIdx.x;
    if (i >= npairs) return;
    float2 v = *(const float2*)(src + (size_t)i * 2);
    dst[i] = packbf2(v.x, v.y);
}
__global__ void convert_split_kernel(const float* __restrict__ src,
                                     uint32_t* __restrict__ hi, uint32_t* __restrict__ lo, int npairs)
{
    int i = blockIdx.x * 256 + threadIdx.x;
    if (i >= npairs) return;
    float2 v = *(const float2*)(src + (size_t)i * 2);
    float hx = bf16r(v.x), hy = bf16r(v.y);
    hi[i] = packbf2(hx, hy);
    lo[i] = packbf2(v.x - hx, v.y - hy);
}

// ---------------- tensor-core NT GEMM, swizzled smem + single-sync pipeline ---
// C[M,N] = A[M,K] * B[N,K]^T, operands pre-split bf16 hi/lo planes.
// Smem: rows of 16 u32 (64B), 16B block b stored at (b ^ ((row>>1)&3)).
// STAGES-deep cp.async pipeline, ONE __syncthreads per K-tile.
template<int HAS_ALO, int CHUNKZ, int STAGES>
__global__ void __launch_bounds__(256) gemm_bf16s_kernel(
    const uint32_t* __restrict__ Ahi_g, const uint32_t* __restrict__ Alo_g,
    const uint32_t* __restrict__ Bhi_g, const uint32_t* __restrict__ Blo_g,
    float* __restrict__ C, int M, int N, int K)
{
    extern __shared__ uint32_t smemu[];
    const uint32_t PS    = STAGES * 2048;                  // plane size, u32
    const uint32_t BHS_O = PS * (1 + (HAS_ALO ? 1 : 0));
    const uint32_t BLS_O = BHS_O + PS;
    uint32_t* Ahs = smemu;
    uint32_t* Als = smemu + PS;
    uint32_t* Bhs = smemu + BHS_O;
    uint32_t* Bls = smemu + BLS_O;

    if (CHUNKZ) {
        size_t cz = blockIdx.z;
        Ahi_g += cz * (size_t)CH * (DSTATE / 2);
        if (HAS_ALO) Alo_g += cz * (size_t)CH * (DSTATE / 2);
        Bhi_g += cz * (size_t)DINNER * (DSTATE / 2);
        Blo_g += cz * (size_t)DINNER * (DSTATE / 2);
        C     += cz * (size_t)CH * DINNER;
    }

    const int K2 = K >> 1;
    const int KT = K2 >> 4;
    const int bn = blockIdx.x * 128;
    const int bm = blockIdx.y * 128;
    const int tid = threadIdx.x;
    const int lane = tid & 31;
    const int wid = tid >> 5;
    const int warpM = wid >> 2;
    const int warpN = wid & 3;
    const int g = lane >> 2;
    const int tig = lane & 3;

    const uint32_t sb32 = (uint32_t)__cvta_generic_to_shared(smemu);
    // per-lane fragment row/bbit (within 128-row tile)
    const int arow = (lane & 15);            // + warpM*64 + mt*16
    const int abit = lane >> 4;
    const int brow = (lane & 7) + ((lane >> 4) << 3);   // + warpN*32 + ntp*16
    const int bbit = (lane >> 3) & 1;

    auto issue = [&](int kt) {
        int k0u = kt * 16;
        uint32_t so = (uint32_t)((kt % STAGES) * 2048);
#pragma unroll
        for (int r = 0; r < 2; r++) {
            int idx = r * 256 + tid;            // 0..511
            int row = idx >> 2;                 // 0..127
            int b = idx & 3;
            uint32_t dsto = so + row * 16 + ((b ^ ((row >> 1) & 3)) << 2);
            size_t ga = (size_t)(bm + row) * K2 + k0u + b * 4;
            cp16(&Ahs[dsto], Ahi_g + ga, 16);
            if (HAS_ALO) cp16(&Als[dsto], Alo_g + ga, 16);
            int nn = bn + row;
            int sz = (nn < N) ? 16 : 0;
            size_t gb = (size_t)((nn < N) ? nn : 0) * K2 + k0u + b * 4;
            cp16(&Bhs[dsto], Bhi_g + gb, sz);
            cp16(&Bls[dsto], Blo_g + gb, sz);
        }
        asm volatile("cp.async.commit_group;" ::: "memory");
    };

    float acc[4][4][4];
#pragma unroll
    for (int mt = 0; mt < 4; mt++)
#pragma unroll
        for (int nt = 0; nt < 4; nt++)
#pragma unroll
            for (int e = 0; e < 4; e++) acc[mt][nt][e] = 0.f;

    auto compute = [&](int kt) {
        const uint32_t so4 = (uint32_t)((kt % STAGES) * 2048) * 4;
#pragma unroll
        for (int kh = 0; kh < 2; kh++) {
            uint32_t bhi[4][2], blo[4][2];
#pragma unroll
            for (int ntp = 0; ntp < 2; ntp++) {
                int row = warpN * 32 + ntp * 16 + brow;
                int b = kh * 2 + bbit;
                uint32_t off = so4 + row * 64 + ((b ^ ((row >> 1) & 3)) << 4);
                ldsm4(bhi[ntp * 2][0], bhi[ntp * 2][1], bhi[ntp * 2 + 1][0], bhi[ntp * 2 + 1][1],
                      sb32 + BHS_O * 4 + off);
                ldsm4(blo[ntp * 2][0], blo[ntp * 2][1], blo[ntp * 2 + 1][0], blo[ntp * 2 + 1][1],
                      sb32 + BLS_O * 4 + off);
            }
#pragma unroll
            for (int mt = 0; mt < 4; mt++) {
                int row = warpM * 64 + mt * 16 + arow;
                int b = kh * 2 + abit;
                uint32_t off = so4 + row * 64 + ((b ^ ((row >> 1) & 3)) << 4);
                uint32_t ah[4], al[4];
                ldsm4(ah[0], ah[1], ah[2], ah[3], sb32 + off);
                if (HAS_ALO) ldsm4(al[0], al[1], al[2], al[3], sb32 + PS * 4 + off);
#pragma unroll
                for (int nt = 0; nt < 4; nt++) MMA_BF16(acc[mt][nt], ah, bhi[nt]);
#pragma unroll
                for (int nt = 0; nt < 4; nt++) MMA_BF16(acc[mt][nt], ah, blo[nt]);
                if (HAS_ALO) {
#pragma unroll
                    for (int nt = 0; nt < 4; nt++) MMA_BF16(acc[mt][nt], al, bhi[nt]);
                }
            }
        }
    };

#pragma unroll
    for (int s = 0; s < STAGES - 1; s++)
        if (s < KT) issue(s);

    for (int kt = 0; kt < KT; kt++) {
        int rem = KT - 1 - kt;
        if (rem >= STAGES - 2) {
            if (STAGES - 2 == 2) asm volatile("cp.async.wait_group 2;" ::: "memory");
            else                 asm volatile("cp.async.wait_group 1;" ::: "memory");
        } else if (rem == 1) {
            asm volatile("cp.async.wait_group 1;" ::: "memory");
        } else {
            asm volatile("cp.async.wait_group 0;" ::: "memory");
        }
        __syncthreads();
        compute(kt);
        if (kt + STAGES - 1 < KT) issue(kt + STAGES - 1);
    }

#pragma unroll
    for (int mt = 0; mt < 4; mt++) {
        int row = bm + warpM * 64 + mt * 16 + g;
#pragma unroll
        for (int nt = 0; nt < 4; nt++) {
            int col = bn + warpN * 32 + nt * 8 + tig * 2;
            if (col < N) {
                C[(size_t)row * N + col]           = acc[mt][nt][0];
                C[(size_t)row * N + col + 1]       = acc[mt][nt][1];
                C[(size_t)(row + 8) * N + col]     = acc[mt][nt][2];
                C[(size_t)(row + 8) * N + col + 1] = acc[mt][nt][3];
            }
        }
    }
}

// ---------------- causal depthwise conv(4) + SiLU + fused C split -------------
__global__ void conv_silu_kernel(const float* __restrict__ cw, const float* __restrict__ cb)
{
    int c = blockIdx.x * 256 + threadIdx.x;
    if (c >= DCONVIN) return;
    int t0 = blockIdx.y * 8;
    float w0 = cw[c * 4], w1 = cw[c * 4 + 1], w2 = cw[c * 4 + 2], w3 = cw[c * 4 + 3];
    float bias = cb[c];
    float v[11];
#pragma unroll
    for (int i = 0; i < 11; i++) {
        int tt = t0 - 3 + i;
        v[i] = (tt >= 0) ? g_zx[(size_t)tt * DPROJ + DINNER + c] : 0.f;
    }
    bool isC = (c >= DINNER + DSTATE);
    int n = c - (DINNER + DSTATE);
#pragma unroll
    for (int i = 0; i < 8; i++) {
        float s = bias + v[i] * w0 + v[i + 1] * w1 + v[i + 2] * w2 + v[i + 3] * w3;
        float a = s / (1.f + expf(-s));
        g_xbc[(size_t)(t0 + i) * DCONVIN + c] = a;
        if (isC) {
            float hi = bf16r(a);
            g_Chi16[(size_t)(t0 + i) * DSTATE + n] = __float2bfloat16(hi);
            g_Clo16[(size_t)(t0 + i) * DSTATE + n] = __float2bfloat16(a - hi);
        }
    }
}

// ---------------- softplus(dt)+dt_bias, dt*A, per-chunk inclusive cumsum ------
__global__ void dtscan_kernel(const float* __restrict__ dt_bias, const float* __restrict__ A_log)
{
    int bid = blockIdx.x;
    int c = bid >> 5, h = bid & 31;
    int s = threadIdx.x;
    int t = c * CH + s;
    float raw = g_zx[(size_t)t * DPROJ + (DINNER + DINNER + 2 * DSTATE) + h] + dt_bias[h];
    float dtv = (raw > 20.f) ? raw : log1pf(expf(raw));
    float Ah = -expf(A_log[h]);
    __shared__ float sm[CH];
    sm[s] = dtv * Ah;
    g_dt[h * SEQ + t] = dtv;
    __syncthreads();
    for (int off = 1; off < CH; off <<= 1) {
        float add = (s >= off) ? sm[s - off] : 0.f;
        __syncthreads();
        sm[s] += add;
        __syncthreads();
    }
    g_L[h * SEQ + t] = sm[s];
}

// ---------------- gram: G[c][s][j] = C_s . B_j --------------------------------
__global__ void __launch_bounds__(256) gram_kernel()
{
    int c = blockIdx.x;
    __shared__ float CsT[16 * 132];
    __shared__ float BsT[16 * 132];
    int tid = threadIdx.x;
    int ts = tid >> 4, tj = tid & 15;
    int base = c * CH;

    float acc[8][8];
#pragma unroll
    for (int i = 0; i < 8; i++)
#pragma unroll
        for (int k = 0; k < 8; k++) acc[i][k] = 0.f;

    for (int n0 = 0; n0 < DSTATE; n0 += 16) {
#pragma unroll
        for (int r = 0; r < 2; r++) {
            int qi = r * 256 + tid;
            int s = qi >> 2, nq = qi & 3;
            float4 vc = *(const float4*)&g_xbc[(size_t)(base + s) * DCONVIN + DINNER + DSTATE + n0 + nq * 4];
            CsT[(nq * 4 + 0) * 132 + s] = vc.x; CsT[(nq * 4 + 1) * 132 + s] = vc.y;
            CsT[(nq * 4 + 2) * 132 + s] = vc.z; CsT[(nq * 4 + 3) * 132 + s] = vc.w;
            float4 vb = *(const float4*)&g_xbc[(size_t)(base + s) * DCONVIN + DINNER + n0 + nq * 4];
            BsT[(nq * 4 + 0) * 132 + s] = vb.x; BsT[(nq * 4 + 1) * 132 + s] = vb.y;
            BsT[(nq * 4 + 2) * 132 + s] = vb.z; BsT[(nq * 4 + 3) * 132 + s] = vb.w;
        }
        __syncthreads();
#pragma unroll
        for (int nn = 0; nn < 16; nn++) {
            float4 c0 = *(float4*)&CsT[nn * 132 + ts * 8];
            float4 c1 = *(float4*)&CsT[nn * 132 + ts * 8 + 4];
            float4 b0 = *(float4*)&BsT[nn * 132 + tj * 8];
            float4 b1 = *(float4*)&BsT[nn * 132 + tj * 8 + 4];
            float cv[8] = {c0.x, c0.y, c0.z, c0.w, c1.x, c1.y, c1.z, c1.w};
            float bv[8] = {b0.x, b0.y, b0.z, b0.w, b1.x, b1.y, b1.z, b1.w};
#pragma unroll
            for (int i = 0; i < 8; i++)
#pragma unroll
                for (int k = 0; k < 8; k++) acc[i][k] += cv[i] * bv[k];
        }
        __syncthreads();
    }
#pragma unroll
    for (int i = 0; i < 8; i++) {
        size_t row = (size_t)(c * CH + ts * 8 + i) * CH;
        *(float4*)&g_Gram[row + tj * 8]     = make_float4(acc[i][0], acc[i][1], acc[i][2], acc[i][3]);
        *(float4*)&g_Gram[row + tj * 8 + 4] = make_float4(acc[i][4], acc[i][5], acc[i][6], acc[i][7]);
    }
}

// ---------------- pass 1 (tensor cores): S[c,h] = (w.X)^T @ B -----------------
#define CS_AH 0
#define CS_AL (128 * 36)
#define CS_BH (2 * 128 * 36)
#define CS_BL (CS_BH + 128 * 68)
#define CS_W  (CS_BL + 128 * 68)
#define CS_SMEM_U32 (CS_W + 128)
__global__ void __launch_bounds__(128) chunkstate_mma_kernel()
{
    extern __shared__ uint32_t cs[];
    float* ws = (float*)(cs + CS_W);
    int bid = blockIdx.x;
    int c = bid >> 5, h = bid & 31;
    int tid = threadIdx.x;
    int lane = tid & 31, wid = tid >> 5;
    int base = c * CH;

    {
        float Lend = g_L[h * SEQ + base + CH - 1];
        ws[tid] = __expf(Lend - g_L[h * SEQ + base + tid]) * g_dt[h * SEQ + base + tid];
    }
    __syncthreads();

    for (int idx = tid; idx < 128 * 16; idx += 128) {
        int j = idx >> 4, p4 = (idx & 15) * 4;
        float4 v = *(const float4*)&g_xbc[(size_t)(base + j) * DCONVIN + h * HD + p4];
        float w = ws[j];
        v.x *= w; v.y *= w; v.z *= w; v.w *= w;
        float hx = bf16r(v.x), hy = bf16r(v.y), hz = bf16r(v.z), hw = bf16r(v.w);
        int o = j * 36 + (p4 >> 1);
        cs[CS_AH + o]     = packbf2(hx, hy);
        cs[CS_AH + o + 1] = packbf2(hz, hw);
        cs[CS_AL + o]     = packbf2(v.x - hx, v.y - hy);
        cs[CS_AL + o + 1] = packbf2(v.z - hz, v.w - hw);
    }
    for (int idx = tid; idx < 128 * 32; idx += 128) {
        int j = idx >> 5, n4 = (idx & 31) * 4;
        float4 v = *(const float4*)&g_xbc[(size_t)(base + j) * DCONVIN + DINNER + n4];
        float hx = bf16r(v.x), hy = bf16r(v.y), hz = bf16r(v.z), hw = bf16r(v.w);
        int o = j * 68 + (n4 >> 1);
        cs[CS_BH + o]     = packbf2(hx, hy);
        cs[CS_BH + o + 1] = packbf2(hz, hw);
        cs[CS_BL + o]     = packbf2(v.x - hx, v.y - hy);
        cs[CS_BL + o + 1] = packbf2(v.z - hz, v.w - hw);
    }
    __syncthreads();

    uint32_t sb = (uint32_t)__cvta_generic_to_shared(cs);
    const uint32_t AOFFT = (((lane & 7) + (lane >> 4) * 8) * 36 + ((lane >> 3) & 1) * 4) * 4;
    const uint32_t BOFFT = (((lane & 7) + ((lane >> 3) & 1) * 8) * 68 + (lane >> 4) * 4) * 4;

    float acc[4][4][4];
#pragma unroll
    for (int mt = 0; mt < 4; mt++)
#pragma unroll
        for (int nt = 0; nt < 4; nt++)
#pragma unroll
            for (int e = 0; e < 4; e++) acc[mt][nt][e] = 0.f;

    for (int ks = 0; ks < 8; ks++) {
        uint32_t bh[4][2], bl[4][2];
#pragma unroll
        for (int np = 0; np < 2; np++) {
            uint32_t nbase = sb + (uint32_t)((ks * 16 * 68) * 4) + (uint32_t)((wid * 32 + np * 16) * 2) + BOFFT;
            ldsm4t(bh[np * 2][0], bh[np * 2][1], bh[np * 2 + 1][0], bh[np * 2 + 1][1],
                   nbase + CS_BH * 4);
            ldsm4t(bl[np * 2][0], bl[np * 2][1], bl[np * 2 + 1][0], bl[np * 2 + 1][1],
                   nbase + CS_BL * 4);
        }
#pragma unroll
        for (int mt = 0; mt < 4; mt++) {
            uint32_t abase = sb + (uint32_t)((ks * 16 * 36) * 4) + (uint32_t)((mt * 16) * 2) + AOFFT;
            uint32_t ah[4], al[4];
            ldsm4t(ah[0], ah[1], ah[2], ah[3], abase + CS_AH * 4);
            ldsm4t(al[0], al[1], al[2], al[3], abase + CS_AL * 4);
#pragma unroll
            for (int nt = 0; nt < 4; nt++) MMA_BF16(acc[mt][nt], ah, bh[nt]);
#pragma unroll
            for (int nt = 0; nt < 4; nt++) MMA_BF16(acc[mt][nt], ah, bl[nt]);
#pragma unroll
            for (int nt = 0; nt < 4; nt++) MMA_BF16(acc[mt][nt], al, bh[nt]);
        }
    }

    int g = lane >> 2, tig = lane & 3;
#pragma unroll
    for (int mt = 0; mt < 4; mt++) {
        int p = mt * 16 + g;
#pragma unroll
        for (int nt = 0; nt < 4; nt++) {
            int n = wid * 32 + nt * 8 + tig * 2;
            size_t row = ((size_t)(c * NH + h) * HD + p) * DSTATE;
            g_S[row + n]     = acc[mt][nt][0];
            g_S[row + n + 1] = acc[mt][nt][1];
            g_S[row + 8 * DSTATE + n]     = acc[mt][nt][2];
            g_S[row + 8 * DSTATE + n + 1] = acc[mt][nt][3];
        }
    }
}

// ---------------- pass 2: 32-step scan; emit H as split bf16 ------------------
__global__ void scan_kernel()
{
    int idx = blockIdx.x * 256 + threadIdx.x;
    int h = idx >> 12;
    int rem = idx & 4095;
    int p = rem >> 6;
    int n2 = (rem & 63) * 2;
    float h0 = 0.f, h1 = 0.f;
    for (int c = 0; c < NCH; c++) {
        size_t row = (size_t)c * DINNER + h * HD + p;
        float b0 = bf16r(h0), b1 = bf16r(h1);
        g_Hhi[row * 64 + (n2 >> 1)] = packbf2(b0, b1);
        g_Hlo[row * 64 + (n2 >> 1)] = packbf2(h0 - b0, h1 - b1);
        float2 s = *(const float2*)&g_S[((size_t)(c * NH + h) * HD + p) * DSTATE + n2];
        float dA = expf(g_L[h * SEQ + c * CH + CH - 1]);
        h0 = dA * h0 + s.x;
        h1 = dA * h1 + s.y;
    }
}

// ---------------- pass 3 (tensor cores + staged epilogue) ---------------------
#define CO_AMH 0
#define CO_AML (128 * 68)
#define CO_XH  (2 * 128 * 68)
#define CO_XL  (CO_XH + 128 * 36)
#define CO_LS  (CO_XL + 128 * 36)
#define CO_DTS (CO_LS + 128)
#define CO_SMEM_U32 (CO_DTS + 128)
__global__ void __launch_bounds__(256) chunkout_mma_kernel(const float* __restrict__ Dvec)
{
    extern __shared__ uint32_t cs[];
    float* Ls  = (float*)(cs + CO_LS);
    float* dts = (float*)(cs + CO_DTS);
    float* Yst = (float*)cs;
    int bid = blockIdx.x;
    int c = bid >> 5, h = bid & 31;
    int tid = threadIdx.x;
    int lane = tid & 31, wid = tid >> 5;
    int base = c * CH;

    if (tid < 128) {
        Ls[tid]  = g_L [h * SEQ + base + tid];
        dts[tid] = g_dt[h * SEQ + base + tid];
    }
    __syncthreads();

    const float* Gc = g_Gram + (size_t)c * CH * CH;
    for (int idx = tid; idx < 128 * 64; idx += 256) {
        int s = idx >> 6;
        int j2 = (idx & 63) * 2;
        float2 gv = *(const float2*)&Gc[(size_t)s * CH + j2];
        float ls = Ls[s];
        float w0 = (j2 <= s)     ? __expf(ls - Ls[j2])     * dts[j2]     : 0.f;
        float w1 = (j2 + 1 <= s) ? __expf(ls - Ls[j2 + 1]) * dts[j2 + 1] : 0.f;
        float v0 = gv.x * w0, v1 = gv.y * w1;
        float h0 = bf16r(v0), h1 = bf16r(v1);
        int o = s * 68 + (j2 >> 1);
        cs[CO_AMH + o] = packbf2(h0, h1);
        cs[CO_AML + o] = packbf2(v0 - h0, v1 - h1);
    }
    for (int idx = tid; idx < 128 * 16; idx += 256) {
        int j = idx >> 4, p4 = (idx & 15) * 4;
        float4 v = *(const float4*)&g_xbc[(size_t)(base + j) * DCONVIN + h * HD + p4];
        float hx = bf16r(v.x), hy = bf16r(v.y), hz = bf16r(v.z), hw = bf16r(v.w);
        int o = j * 36 + (p4 >> 1);
        cs[CO_XH + o]     = packbf2(hx, hy);
        cs[CO_XH + o + 1] = packbf2(hz, hw);
        cs[CO_XL + o]     = packbf2(v.x - hx, v.y - hy);
        cs[CO_XL + o + 1] = packbf2(v.z - hz, v.w - hw);
    }
    __syncthreads();

    uint32_t sb = (uint32_t)__cvta_generic_to_shared(cs);
    const uint32_t AOFF = ((lane & 15) * 68 + (lane >> 4) * 4) * 4;
    const uint32_t BOFFT = (((lane & 7) + ((lane >> 3) & 1) * 8) * 36 + (lane >> 4) * 4) * 4;

    float acc[8][2][4];
    if (wid < 4) {
#pragma unroll
        for (int mt = 0; mt < 8; mt++)
#pragma unroll
            for (int nt = 0; nt < 2; nt++)
#pragma unroll
                for (int e = 0; e < 4; e++) acc[mt][nt][e] = 0.f;

        for (int ks = 0; ks < 8; ks++) {
            uint32_t bh[2][2], bl[2][2];
            uint32_t nbase = sb + (uint32_t)((ks * 16 * 36) * 4) + (uint32_t)((wid * 16) * 2) + BOFFT;
            ldsm4t(bh[0][0], bh[0][1], bh[1][0], bh[1][1], nbase + CO_XH * 4);
            ldsm4t(bl[0][0], bl[0][1], bl[1][0], bl[1][1], nbase + CO_XL * 4);
#pragma unroll
            for (int mt = 0; mt < 8; mt++) {
                uint32_t abase = sb + (uint32_t)((mt * 16 * 68) * 4) + (uint32_t)((ks * 8) * 4) + AOFF;
                uint32_t ah[4], al[4];
                ldsm4(ah[0], ah[1], ah[2], ah[3], abase + CO_AMH * 4);
                ldsm4(al[0], al[1], al[2], al[3], abase + CO_AML * 4);
#pragma unroll
                for (int nt = 0; nt < 2; nt++) MMA_BF16(acc[mt][nt], ah, bh[nt]);
#pragma unroll
                for (int nt = 0; nt < 2; nt++) MMA_BF16(acc[mt][nt], ah, bl[nt]);
#pragma unroll
                for (int nt = 0; nt < 2; nt++) MMA_BF16(acc[mt][nt], al, bh[nt]);
            }
        }
    }
    __syncthreads();

    if (wid < 4) {
        int g = lane >> 2, tig = lane & 3;
#pragma unroll
        for (int mt = 0; mt < 8; mt++) {
            int s0 = mt * 16 + g;
#pragma unroll
            for (int nt = 0; nt < 2; nt++) {
                int p = wid * 16 + nt * 8 + tig * 2;
                *(float2*)&Yst[s0 * 68 + p]       = make_float2(acc[mt][nt][0], acc[mt][nt][1]);
                *(float2*)&Yst[(s0 + 8) * 68 + p] = make_float2(acc[mt][nt][2], acc[mt][nt][3]);
            }
        }
    }
    __syncthreads();

    float Dh = Dvec[h];
    for (int idx = tid; idx < 128 * 16; idx += 256) {
        int s = idx >> 4, p4 = (idx & 15) * 4;
        int trow = base + s;
        float es = expf(Ls[s]);
        float4 yv = *(float4*)&Yst[s * 68 + p4];
        float4 xv = *(const float4*)&g_xbc[(size_t)trow * DCONVIN + h * HD + p4];
        float4 iv = *(const float4*)&g_Inter[((size_t)(c * CH + s)) * DINNER + h * HD + p4];
        float4 ov;
        ov.x = yv.x + es * iv.x + Dh * xv.x;
        ov.y = yv.y + es * iv.y + Dh * xv.y;
        ov.z = yv.z + es * iv.z + Dh * xv.z;
        ov.w = yv.w + es * iv.w + Dh * xv.w;
        *(float4*)&g_Y[(size_t)trow * DINNER + h * HD + p4] = ov;
    }
}

// ---------------- RMSNorm + SiLU gate -> split bf16 ---------------------------
__global__ void normgate_kernel(const float* __restrict__ nw, const float* __restrict__ nb)
{
    int t = blockIdx.x;
    int tid = threadIdx.x;
    __shared__ float red[256];
    float ss = 0.f;
    for (int d = tid; d < DINNER; d += 256) {
        float v = g_Y[(size_t)t * DINNER + d];
        ss += v * v;
    }
    red[tid] = ss;
    __syncthreads();
    for (int off = 128; off > 0; off >>= 1) {
        if (tid < off) red[tid] += red[tid + off];
        __syncthreads();
    }
    float inv = rsqrtf(red[0] / (float)DINNER + 1e-6f);
    for (int d = tid * 2; d < DINNER; d += 512) {
        float v0 = g_Y[(size_t)t * DINNER + d];
        float v1 = g_Y[(size_t)t * DINNER + d + 1];
        float g0 = v0 * inv * nw[d] + nb[d];
        float g1 = v1 * inv * nw[d + 1] + nb[d + 1];
        float z0 = g_zx[(size_t)t * DPROJ + d];
        float z1 = g_zx[(size_t)t * DPROJ + d + 1];
        g0 *= z0 / (1.f + expf(-z0));
        g1 *= z1 / (1.f + expf(-z1));
        float h0 = bf16r(g0), h1 = bf16r(g1);
        size_t pi = ((size_t)t * DINNER + d) >> 1;
        g_Ghi[pi] = packbf2(h0, h1);
        g_Glo[pi] = packbf2(g0 - h0, g1 - h1);
    }
}

// ---------------- launch ------------------------------------------------------
extern "C" void kernel_launch(void* const* d_in, const int* in_sizes, int n_in,
                              void* d_out, int out_size)
{
    const float* u       = (const float*)d_in[0];
    const float* W_in    = (const float*)d_in[1];
    const float* conv_w  = (const float*)d_in[2];
    const float* conv_b  = (const float*)d_in[3];
    const float* W_out   = (const float*)d_in[4];
    const float* norm_w  = (const float*)d_in[5];
    const float* norm_b  = (const float*)d_in[6];
    const float* dt_bias = (const float*)d_in[7];
    const float* A_log   = (const float*)d_in[8];
    const float* Dv      = (const float*)d_in[9];
    float* out = (float*)d_out;

    float *zx, *Inter;
    uint32_t *u16, *Whi, *Wlo, *Vhi, *Vlo, *Ghi, *Glo, *Hhi, *Hlo, *Chi, *Clo;
    cudaGetSymbolAddress((void**)&zx,   g_zx);
    cudaGetSymbolAddress((void**)&Inter,g_Inter);
    cudaGetSymbolAddress((void**)&u16,  g_u16);
    cudaGetSymbolAddress((void**)&Whi,  g_Whi);
    cudaGetSymbolAddress((void**)&Wlo,  g_Wlo);
    cudaGetSymbolAddress((void**)&Vhi,  g_Vhi);
    cudaGetSymbolAddress((void**)&Vlo,  g_Vlo);
    cudaGetSymbolAddress((void**)&Ghi,  g_Ghi);
    cudaGetSymbolAddress((void**)&Glo,  g_Glo);
    cudaGetSymbolAddress((void**)&Hhi,  g_Hhi);
    cudaGetSymbolAddress((void**)&Hlo,  g_Hlo);
    cudaGetSymbolAddress((void**)&Chi,  g_Chi16);
    cudaGetSymbolAddress((void**)&Clo,  g_Clo16);

    const int SM1 = 3 * 4 * 8192;   // gemm<0,0,4>: 3 planes x 4 stages x 8KB
    const int SM2 = 4 * 3 * 8192;   // gemm<1,*,3>: 4 planes x 3 stages x 8KB
    const int SMC = CS_SMEM_U32 * 4;
    const int SMO = CO_SMEM_U32 * 4;
    cudaFuncSetAttribute(gemm_bf16s_kernel<0, 0, 4>, cudaFuncAttributeMaxDynamicSharedMemorySize, SM1);
    cudaFuncSetAttribute(gemm_bf16s_kernel<1, 0, 3>, cudaFuncAttributeMaxDynamicSharedMemorySize, SM2);
    cudaFuncSetAttribute(gemm_bf16s_kernel<1, 1, 3>, cudaFuncAttributeMaxDynamicSharedMemorySize, SM2);
    cudaFuncSetAttribute(chunkstate_mma_kernel, cudaFuncAttributeMaxDynamicSharedMemorySize, SMC);
    cudaFuncSetAttribute(chunkout_mma_kernel, cudaFuncAttributeMaxDynamicSharedMemorySize, SMO);

    // 0. pre-convert operands
    {
        int np;
        np = SEQ * DMODEL / 2;
        convert_round_kernel<<<(np + 255) / 256, 256>>>(u, u16, np);
        np = DPROJ * DMODEL / 2;
        convert_split_kernel<<<(np + 255) / 256, 256>>>(W_in, Whi, Wlo, np);
        np = DMODEL * DINNER / 2;
        convert_split_kernel<<<(np + 255) / 256, 256>>>(W_out, Vhi, Vlo, np);
    }
    // 1. in_proj GEMM (4-stage single-sync swizzled pipeline, 2 mma)
    gemm_bf16s_kernel<0, 0, 4><<<dim3((DPROJ + 127) / 128, SEQ / 128), 256, SM1>>>(
        u16, nullptr, Whi, Wlo, zx, SEQ, DPROJ, DMODEL);
    // 2. causal depthwise conv + silu (+ fused C split)
    conv_silu_kernel<<<dim3((DCONVIN + 255) / 256, SEQ / 8), 256>>>(conv_w, conv_b);
    // 3. dt softplus + per-chunk cumsum
    dtscan_kernel<<<NCH * NH, CH>>>(dt_bias, A_log);
    // 3b. gram matrices
    gram_kernel<<<NCH, 256>>>();
    // 4. chunk-local states (mma.sync TC)
    chunkstate_mma_kernel<<<NCH * NH, 128, SMC>>>();
    // 5. inter-chunk scan
    scan_kernel<<<(NH * HD * (DSTATE / 2)) / 256, 256>>>();
    // 5b. inter term (batched, 3-stage single-sync)
    gemm_bf16s_kernel<1, 1, 3><<<dim3(DINNER / 128, 1, NCH), 256, SM2>>>(
        Chi, Clo, Hhi, Hlo, Inter, CH, DINNER, DSTATE);
    // 6. per-chunk output
    chunkout_mma_kernel<<<NCH * NH, 256, SMO>>>(Dv);
    // 7. RMSNorm + gate
    normgate_kernel<<<SEQ, 256>>>(norm_w, norm_b);
    // 8. out_proj GEMM (3-stage single-sync swizzled pipeline, 3 mma)
    gemm_bf16s_kernel<1, 0, 3><<<dim3(DMODEL / 128, SEQ / 128), 256, SM2>>>(
        Ghi, Glo, Vhi, Vlo, out, SEQ, DMODEL, DINNER);
}

// round 15
// speedup vs baseline: 1.2415x; 1.0035x over previous
#include <cuda_runtime.h>
#include <cuda_bf16.h>
#include <cstdint>

#define SEQ     4096
#define DMODEL  1024
#define DPROJ   4384
#define DINNER  2048
#define DCONVIN 2304
#define DSTATE  128
#define NH      32
#define HD      64
#define NCH     32
#define CH      128

// ---------------- scratch (static __device__, allocation-free) ----------------
__device__ float g_zx [SEQ * DPROJ];
__device__ float g_xbc[SEQ * DCONVIN];
__device__ float g_dt [NH * SEQ];
__device__ float g_L  [NH * SEQ];
__device__ float g_S  [NCH * NH * HD * DSTATE];
__device__ float g_Y  [SEQ * DINNER];
__device__ float g_Gram[NCH * CH * CH];
__device__ float g_Inter[NCH * CH * DINNER];

__device__ uint32_t g_u16[SEQ * DMODEL / 2];
__device__ uint32_t g_Whi[DPROJ * DMODEL / 2];
__device__ uint32_t g_Wlo[DPROJ * DMODEL / 2];
__device__ uint32_t g_Vhi[DMODEL * DINNER / 2];
__device__ uint32_t g_Vlo[DMODEL * DINNER / 2];
__device__ uint32_t g_Ghi[SEQ * DINNER / 2];
__device__ uint32_t g_Glo[SEQ * DINNER / 2];
__device__ uint32_t g_Hhi[NCH * DINNER * DSTATE / 2];
__device__ uint32_t g_Hlo[NCH * DINNER * DSTATE / 2];
__device__ __nv_bfloat16 g_Chi16[SEQ * DSTATE];
__device__ __nv_bfloat16 g_Clo16[SEQ * DSTATE];

__device__ __forceinline__ float bf16r(float x) {
    return __bfloat162float(__float2bfloat16(x));
}
__device__ __forceinline__ uint32_t packbf2(float x, float y) {
    __nv_bfloat162 t = __floats2bfloat162_rn(x, y);
    return *(uint32_t*)&t;
}
__device__ __forceinline__ void cp16(void* sdst, const void* gsrc, int sz) {
    uint32_t sa = (uint32_t)__cvta_generic_to_shared(sdst);
    asm volatile("cp.async.cg.shared.global [%0], [%1], 16, %2;" :: "r"(sa), "l"(gsrc), "r"(sz));
}
__device__ __forceinline__ void ldsm4(uint32_t& r0, uint32_t& r1, uint32_t& r2, uint32_t& r3,
                                      uint32_t saddr) {
    asm volatile("ldmatrix.sync.aligned.m8n8.x4.shared.b16 {%0,%1,%2,%3}, [%4];"
                 : "=r"(r0), "=r"(r1), "=r"(r2), "=r"(r3) : "r"(saddr));
}
__device__ __forceinline__ void ldsm4t(uint32_t& r0, uint32_t& r1, uint32_t& r2, uint32_t& r3,
                                       uint32_t saddr) {
    asm volatile("ldmatrix.sync.aligned.m8n8.x4.trans.shared.b16 {%0,%1,%2,%3}, [%4];"
                 : "=r"(r0), "=r"(r1), "=r"(r2), "=r"(r3) : "r"(saddr));
}

#define MMA_BF16(d, a, b)                                                        \
    asm volatile("mma.sync.aligned.m16n8k16.row.col.f32.bf16.bf16.f32 "          \
                 "{%0,%1,%2,%3}, {%4,%5,%6,%7}, {%8,%9}, {%0,%1,%2,%3};"         \
                 : "+f"(d[0]), "+f"(d[1]), "+f"(d[2]), "+f"(d[3])                \
                 : "r"(a[0]), "r"(a[1]), "r"(a[2]), "r"(a[3]),                   \
                   "r"(b[0]), "r"(b[1]))

// ---------------- fused operand conversion ------------------------------------
#define NP_U (SEQ * DMODEL / 2)
#define NP_W (DPROJ * DMODEL / 2)
#define NP_V (DMODEL * DINNER / 2)
__global__ void convert_all_kernel(const float* __restrict__ u,
                                   const float* __restrict__ W_in,
                                   const float* __restrict__ W_out)
{
    int i = blockIdx.x * 256 + threadIdx.x;
    if (i < NP_U) {
        float2 v = *(const float2*)(u + (size_t)i * 2);
        g_u16[i] = packbf2(v.x, v.y);
    } else if (i < NP_U + NP_W) {
        int j = i - NP_U;
        float2 v = *(const float2*)(W_in + (size_t)j * 2);
        float hx = bf16r(v.x), hy = bf16r(v.y);
        g_Whi[j] = packbf2(hx, hy);
        g_Wlo[j] = packbf2(v.x - hx, v.y - hy);
    } else if (i < NP_U + NP_W + NP_V) {
        int j = i - NP_U - NP_W;
        float2 v = *(const float2*)(W_out + (size_t)j * 2);
        float hx = bf16r(v.x), hy = bf16r(v.y);
        g_Vhi[j] = packbf2(hx, hy);
        g_Vlo[j] = packbf2(v.x - hx, v.y - hy);
    }
}

// ---------------- tensor-core NT GEMM, swizzled smem, pipelined ---------------
// C[M,N] = A[M,K] * B[N,K]^T, operands pre-split bf16 hi/lo planes.
// Smem: rows of 16 u32 (64B), 16B block b stored at (b ^ ((row>>1)&3)).
// TWO_TILE=1 (requires STAGES=4, KT even): one barrier per TWO K-tiles,
//   issue-before-compute ordering (WAR-safe: buffer (kt+2)%4 last read in
//   compute(kt-2), finished before this iteration's sync).
template<int HAS_ALO, int CHUNKZ, int STAGES, int TWO_TILE = 0>
__global__ void __launch_bounds__(256) gemm_bf16s_kernel(
    const uint32_t* __restrict__ Ahi_g, const uint32_t* __restrict__ Alo_g,
    const uint32_t* __restrict__ Bhi_g, const uint32_t* __restrict__ Blo_g,
    float* __restrict__ C, int M, int N, int K)
{
    extern __shared__ uint32_t smemu[];
    const uint32_t PS    = STAGES * 2048;
    const uint32_t BHS_O = PS * (1 + (HAS_ALO ? 1 : 0));
    const uint32_t BLS_O = BHS_O + PS;
    uint32_t* Ahs = smemu;
    uint32_t* Als = smemu + PS;
    uint32_t* Bhs = smemu + BHS_O;
    uint32_t* Bls = smemu + BLS_O;

    if (CHUNKZ) {
        size_t cz = blockIdx.z;
        Ahi_g += cz * (size_t)CH * (DSTATE / 2);
        if (HAS_ALO) Alo_g += cz * (size_t)CH * (DSTATE / 2);
        Bhi_g += cz * (size_t)DINNER * (DSTATE / 2);
        Blo_g += cz * (size_t)DINNER * (DSTATE / 2);
        C     += cz * (size_t)CH * DINNER;
    }

    const int K2 = K >> 1;
    const int KT = K2 >> 4;
    const int bn = blockIdx.x * 128;
    const int bm = blockIdx.y * 128;
    const int tid = threadIdx.x;
    const int lane = tid & 31;
    const int wid = tid >> 5;
    const int warpM = wid >> 2;
    const int warpN = wid & 3;
    const int g = lane >> 2;
    const int tig = lane & 3;

    const uint32_t sb32 = (uint32_t)__cvta_generic_to_shared(smemu);
    const int arow = (lane & 15);
    const int abit = lane >> 4;
    const int brow = (lane & 7) + ((lane >> 4) << 3);
    const int bbit = (lane >> 3) & 1;

    auto issue = [&](int kt) {
        int k0u = kt * 16;
        uint32_t so = (uint32_t)((kt % STAGES) * 2048);
#pragma unroll
        for (int r = 0; r < 2; r++) {
            int idx = r * 256 + tid;
            int row = idx >> 2;
            int b = idx & 3;
            uint32_t dsto = so + row * 16 + ((b ^ ((row >> 1) & 3)) << 2);
            size_t ga = (size_t)(bm + row) * K2 + k0u + b * 4;
            cp16(&Ahs[dsto], Ahi_g + ga, 16);
            if (HAS_ALO) cp16(&Als[dsto], Alo_g + ga, 16);
            int nn = bn + row;
            int sz = (nn < N) ? 16 : 0;
            size_t gb = (size_t)((nn < N) ? nn : 0) * K2 + k0u + b * 4;
            cp16(&Bhs[dsto], Bhi_g + gb, sz);
            cp16(&Bls[dsto], Blo_g + gb, sz);
        }
        asm volatile("cp.async.commit_group;" ::: "memory");
    };

    float acc[4][4][4];
#pragma unroll
    for (int mt = 0; mt < 4; mt++)
#pragma unroll
        for (int nt = 0; nt < 4; nt++)
#pragma unroll
            for (int e = 0; e < 4; e++) acc[mt][nt][e] = 0.f;

    auto compute = [&](int kt) {
        const uint32_t so4 = (uint32_t)((kt % STAGES) * 2048) * 4;
#pragma unroll
        for (int kh = 0; kh < 2; kh++) {
            uint32_t bhi[4][2], blo[4][2];
#pragma unroll
            for (int ntp = 0; ntp < 2; ntp++) {
                int row = warpN * 32 + ntp * 16 + brow;
                int b = kh * 2 + bbit;
                uint32_t off = so4 + row * 64 + ((b ^ ((row >> 1) & 3)) << 4);
                ldsm4(bhi[ntp * 2][0], bhi[ntp * 2][1], bhi[ntp * 2 + 1][0], bhi[ntp * 2 + 1][1],
                      sb32 + BHS_O * 4 + off);
                ldsm4(blo[ntp * 2][0], blo[ntp * 2][1], blo[ntp * 2 + 1][0], blo[ntp * 2 + 1][1],
                      sb32 + BLS_O * 4 + off);
            }
#pragma unroll
            for (int mt = 0; mt < 4; mt++) {
                int row = warpM * 64 + mt * 16 + arow;
                int b = kh * 2 + abit;
                uint32_t off = so4 + row * 64 + ((b ^ ((row >> 1) & 3)) << 4);
                uint32_t ah[4], al[4];
                ldsm4(ah[0], ah[1], ah[2], ah[3], sb32 + off);
                if (HAS_ALO) ldsm4(al[0], al[1], al[2], al[3], sb32 + PS * 4 + off);
#pragma unroll
                for (int nt = 0; nt < 4; nt++) MMA_BF16(acc[mt][nt], ah, bhi[nt]);
#pragma unroll
                for (int nt = 0; nt < 4; nt++) MMA_BF16(acc[mt][nt], ah, blo[nt]);
                if (HAS_ALO) {
#pragma unroll
                    for (int nt = 0; nt < 4; nt++) MMA_BF16(acc[mt][nt], al, bhi[nt]);
                }
            }
        }
    };

    if (TWO_TILE) {
        // STAGES==4, KT even, KT>=4
        issue(0);
        issue(1);
        for (int kt = 0; kt < KT; kt += 2) {
            asm volatile("cp.async.wait_group 0;" ::: "memory");
            __syncthreads();
            if (kt + 2 < KT) { issue(kt + 2); issue(kt + 3); }
            compute(kt);
            compute(kt + 1);
        }
    } else {
#pragma unroll
        for (int s = 0; s < STAGES - 1; s++)
            if (s < KT) issue(s);

        for (int kt = 0; kt < KT; kt++) {
            int rem = KT - 1 - kt;
            if (rem >= STAGES - 2) {
                if (STAGES - 2 == 2) asm volatile("cp.async.wait_group 2;" ::: "memory");
                else                 asm volatile("cp.async.wait_group 1;" ::: "memory");
            } else if (rem == 1) {
                asm volatile("cp.async.wait_group 1;" ::: "memory");
            } else {
                asm volatile("cp.async.wait_group 0;" ::: "memory");
            }
            __syncthreads();
            compute(kt);
            if (kt + STAGES - 1 < KT) issue(kt + STAGES - 1);
        }
    }

#pragma unroll
    for (int mt = 0; mt < 4; mt++) {
        int row = bm + warpM * 64 + mt * 16 + g;
#pragma unroll
        for (int nt = 0; nt < 4; nt++) {
            int col = bn + warpN * 32 + nt * 8 + tig * 2;
            if (col < N) {
                C[(size_t)row * N + col]           = acc[mt][nt][0];
                C[(size_t)row * N + col + 1]       = acc[mt][nt][1];
                C[(size_t)(row + 8) * N + col]     = acc[mt][nt][2];
                C[(size_t)(row + 8) * N + col + 1] = acc[mt][nt][3];
            }
        }
    }
}

// ---------------- causal depthwise conv(4) + SiLU + fused C split -------------
__global__ void conv_silu_kernel(const float* __restrict__ cw, const float* __restrict__ cb)
{
    int c = blockIdx.x * 256 + threadIdx.x;
    if (c >= DCONVIN) return;
    int t0 = blockIdx.y * 8;
    float w0 = cw[c * 4], w1 = cw[c * 4 + 1], w2 = cw[c * 4 + 2], w3 = cw[c * 4 + 3];
    float bias = cb[c];
    float v[11];
#pragma unroll
    for (int i = 0; i < 11; i++) {
        int tt = t0 - 3 + i;
        v[i] = (tt >= 0) ? g_zx[(size_t)tt * DPROJ + DINNER + c] : 0.f;
    }
    bool isC = (c >= DINNER + DSTATE);
    int n = c - (DINNER + DSTATE);
#pragma unroll
    for (int i = 0; i < 8; i++) {
        float s = bias + v[i] * w0 + v[i + 1] * w1 + v[i + 2] * w2 + v[i + 3] * w3;
        float a = s / (1.f + expf(-s));
        g_xbc[(size_t)(t0 + i) * DCONVIN + c] = a;
        if (isC) {
            float hi = bf16r(a);
            g_Chi16[(size_t)(t0 + i) * DSTATE + n] = __float2bfloat16(hi);
            g_Clo16[(size_t)(t0 + i) * DSTATE + n] = __float2bfloat16(a - hi);
        }
    }
}

// ---------------- softplus(dt)+dt_bias, dt*A, per-chunk inclusive cumsum ------
__global__ void dtscan_kernel(const float* __restrict__ dt_bias, const float* __restrict__ A_log)
{
    int bid = blockIdx.x;
    int c = bid >> 5, h = bid & 31;
    int s = threadIdx.x;
    int t = c * CH + s;
    float raw = g_zx[(size_t)t * DPROJ + (DINNER + DINNER + 2 * DSTATE) + h] + dt_bias[h];
    float dtv = (raw > 20.f) ? raw : log1pf(expf(raw));
    float Ah = -expf(A_log[h]);
    __shared__ float sm[CH];
    sm[s] = dtv * Ah;
    g_dt[h * SEQ + t] = dtv;
    __syncthreads();
    for (int off = 1; off < CH; off <<= 1) {
        float add = (s >= off) ? sm[s - off] : 0.f;
        __syncthreads();
        sm[s] += add;
        __syncthreads();
    }
    g_L[h * SEQ + t] = sm[s];
}

// ---------------- gram: G[c][s][j] = C_s . B_j --------------------------------
__global__ void __launch_bounds__(256) gram_kernel()
{
    int c = blockIdx.x;
    __shared__ float CsT[16 * 132];
    __shared__ float BsT[16 * 132];
    int tid = threadIdx.x;
    int ts = tid >> 4, tj = tid & 15;
    int base = c * CH;

    float acc[8][8];
#pragma unroll
    for (int i = 0; i < 8; i++)
#pragma unroll
        for (int k = 0; k < 8; k++) acc[i][k] = 0.f;

    for (int n0 = 0; n0 < DSTATE; n0 += 16) {
#pragma unroll
        for (int r = 0; r < 2; r++) {
            int qi = r * 256 + tid;
            int s = qi >> 2, nq = qi & 3;
            float4 vc = *(const float4*)&g_xbc[(size_t)(base + s) * DCONVIN + DINNER + DSTATE + n0 + nq * 4];
            CsT[(nq * 4 + 0) * 132 + s] = vc.x; CsT[(nq * 4 + 1) * 132 + s] = vc.y;
            CsT[(nq * 4 + 2) * 132 + s] = vc.z; CsT[(nq * 4 + 3) * 132 + s] = vc.w;
            float4 vb = *(const float4*)&g_xbc[(size_t)(base + s) * DCONVIN + DINNER + n0 + nq * 4];
            BsT[(nq * 4 + 0) * 132 + s] = vb.x; BsT[(nq * 4 + 1) * 132 + s] = vb.y;
            BsT[(nq * 4 + 2) * 132 + s] = vb.z; BsT[(nq * 4 + 3) * 132 + s] = vb.w;
        }
        __syncthreads();
#pragma unroll
        for (int nn = 0; nn < 16; nn++) {
            float4 c0 = *(float4*)&CsT[nn * 132 + ts * 8];
            float4 c1 = *(float4*)&CsT[nn * 132 + ts * 8 + 4];
            float4 b0 = *(float4*)&BsT[nn * 132 + tj * 8];
            float4 b1 = *(float4*)&BsT[nn * 132 + tj * 8 + 4];
            float cv[8] = {c0.x, c0.y, c0.z, c0.w, c1.x, c1.y, c1.z, c1.w};
            float bv[8] = {b0.x, b0.y, b0.z, b0.w, b1.x, b1.y, b1.z, b1.w};
#pragma unroll
            for (int i = 0; i < 8; i++)
#pragma unroll
                for (int k = 0; k < 8; k++) acc[i][k] += cv[i] * bv[k];
        }
        __syncthreads();
    }
#pragma unroll
    for (int i = 0; i < 8; i++) {
        size_t row = (size_t)(c * CH + ts * 8 + i) * CH;
        *(float4*)&g_Gram[row + tj * 8]     = make_float4(acc[i][0], acc[i][1], acc[i][2], acc[i][3]);
        *(float4*)&g_Gram[row + tj * 8 + 4] = make_float4(acc[i][4], acc[i][5], acc[i][6], acc[i][7]);
    }
}

// ---------------- pass 1 (tensor cores): S[c,h] = (w.X)^T @ B -----------------
#define CS_AH 0
#define CS_AL (128 * 36)
#define CS_BH (2 * 128 * 36)
#define CS_BL (CS_BH + 128 * 68)
#define CS_W  (CS_BL + 128 * 68)
#define CS_SMEM_U32 (CS_W + 128)
__global__ void __launch_bounds__(128) chunkstate_mma_kernel()
{
    extern __shared__ uint32_t cs[];
    float* ws = (float*)(cs + CS_W);
    int bid = blockIdx.x;
    int c = bid >> 5, h = bid & 31;
    int tid = threadIdx.x;
    int lane = tid & 31, wid = tid >> 5;
    int base = c * CH;

    {
        float Lend = g_L[h * SEQ + base + CH - 1];
        ws[tid] = __expf(Lend - g_L[h * SEQ + base + tid]) * g_dt[h * SEQ + base + tid];
    }
    __syncthreads();

    for (int idx = tid; idx < 128 * 16; idx += 128) {
        int j = idx >> 4, p4 = (idx & 15) * 4;
        float4 v = *(const float4*)&g_xbc[(size_t)(base + j) * DCONVIN + h * HD + p4];
        float w = ws[j];
        v.x *= w; v.y *= w; v.z *= w; v.w *= w;
        float hx = bf16r(v.x), hy = bf16r(v.y), hz = bf16r(v.z), hw = bf16r(v.w);
        int o = j * 36 + (p4 >> 1);
        cs[CS_AH + o]     = packbf2(hx, hy);
        cs[CS_AH + o + 1] = packbf2(hz, hw);
        cs[CS_AL + o]     = packbf2(v.x - hx, v.y - hy);
        cs[CS_AL + o + 1] = packbf2(v.z - hz, v.w - hw);
    }
    for (int idx = tid; idx < 128 * 32; idx += 128) {
        int j = idx >> 5, n4 = (idx & 31) * 4;
        float4 v = *(const float4*)&g_xbc[(size_t)(base + j) * DCONVIN + DINNER + n4];
        float hx = bf16r(v.x), hy = bf16r(v.y), hz = bf16r(v.z), hw = bf16r(v.w);
        int o = j * 68 + (n4 >> 1);
        cs[CS_BH + o]     = packbf2(hx, hy);
        cs[CS_BH + o + 1] = packbf2(hz, hw);
        cs[CS_BL + o]     = packbf2(v.x - hx, v.y - hy);
        cs[CS_BL + o + 1] = packbf2(v.z - hz, v.w - hw);
    }
    __syncthreads();

    uint32_t sb = (uint32_t)__cvta_generic_to_shared(cs);
    const uint32_t AOFFT = (((lane & 7) + (lane >> 4) * 8) * 36 + ((lane >> 3) & 1) * 4) * 4;
    const uint32_t BOFFT = (((lane & 7) + ((lane >> 3) & 1) * 8) * 68 + (lane >> 4) * 4) * 4;

    float acc[4][4][4];
#pragma unroll
    for (int mt = 0; mt < 4; mt++)
#pragma unroll
        for (int nt = 0; nt < 4; nt++)
#pragma unroll
            for (int e = 0; e < 4; e++) acc[mt][nt][e] = 0.f;

    for (int ks = 0; ks < 8; ks++) {
        uint32_t bh[4][2], bl[4][2];
#pragma unroll
        for (int np = 0; np < 2; np++) {
            uint32_t nbase = sb + (uint32_t)((ks * 16 * 68) * 4) + (uint32_t)((wid * 32 + np * 16) * 2) + BOFFT;
            ldsm4t(bh[np * 2][0], bh[np * 2][1], bh[np * 2 + 1][0], bh[np * 2 + 1][1],
                   nbase + CS_BH * 4);
            ldsm4t(bl[np * 2][0], bl[np * 2][1], bl[np * 2 + 1][0], bl[np * 2 + 1][1],
                   nbase + CS_BL * 4);
        }
#pragma unroll
        for (int mt = 0; mt < 4; mt++) {
            uint32_t abase = sb + (uint32_t)((ks * 16 * 36) * 4) + (uint32_t)((mt * 16) * 2) + AOFFT;
            uint32_t ah[4], al[4];
            ldsm4t(ah[0], ah[1], ah[2], ah[3], abase + CS_AH * 4);
            ldsm4t(al[0], al[1], al[2], al[3], abase + CS_AL * 4);
#pragma unroll
            for (int nt = 0; nt < 4; nt++) MMA_BF16(acc[mt][nt], ah, bh[nt]);
#pragma unroll
            for (int nt = 0; nt < 4; nt++) MMA_BF16(acc[mt][nt], ah, bl[nt]);
#pragma unroll
            for (int nt = 0; nt < 4; nt++) MMA_BF16(acc[mt][nt], al, bh[nt]);
        }
    }

    int g = lane >> 2, tig = lane & 3;
#pragma unroll
    for (int mt = 0; mt < 4; mt++) {
        int p = mt * 16 + g;
#pragma unroll
        for (int nt = 0; nt < 4; nt++) {
            int n = wid * 32 + nt * 8 + tig * 2;
            size_t row = ((size_t)(c * NH + h) * HD + p) * DSTATE;
            g_S[row + n]     = acc[mt][nt][0];
            g_S[row + n + 1] = acc[mt][nt][1];
            g_S[row + 8 * DSTATE + n]     = acc[mt][nt][2];
            g_S[row + 8 * DSTATE + n + 1] = acc[mt][nt][3];
        }
    }
}

// ---------------- pass 2: 32-step scan; emit H as split bf16 ------------------
__global__ void scan_kernel()
{
    int idx = blockIdx.x * 256 + threadIdx.x;
    int h = idx >> 12;
    int rem = idx & 4095;
    int p = rem >> 6;
    int n2 = (rem & 63) * 2;
    float h0 = 0.f, h1 = 0.f;
    for (int c = 0; c < NCH; c++) {
        size_t row = (size_t)c * DINNER + h * HD + p;
        float b0 = bf16r(h0), b1 = bf16r(h1);
        g_Hhi[row * 64 + (n2 >> 1)] = packbf2(b0, b1);
        g_Hlo[row * 64 + (n2 >> 1)] = packbf2(h0 - b0, h1 - b1);
        float2 s = *(const float2*)&g_S[((size_t)(c * NH + h) * HD + p) * DSTATE + n2];
        float dA = expf(g_L[h * SEQ + c * CH + CH - 1]);
        h0 = dA * h0 + s.x;
        h1 = dA * h1 + s.y;
    }
}

// ---------------- pass 3 (tensor cores + staged epilogue) ---------------------
#define CO_AMH 0
#define CO_AML (128 * 68)
#define CO_XH  (2 * 128 * 68)
#define CO_XL  (CO_XH + 128 * 36)
#define CO_LS  (CO_XL + 128 * 36)
#define CO_DTS (CO_LS + 128)
#define CO_SMEM_U32 (CO_DTS + 128)
__global__ void __launch_bounds__(256) chunkout_mma_kernel(const float* __restrict__ Dvec)
{
    extern __shared__ uint32_t cs[];
    float* Ls  = (float*)(cs + CO_LS);
    float* dts = (float*)(cs + CO_DTS);
    float* Yst = (float*)cs;
    int bid = blockIdx.x;
    int c = bid >> 5, h = bid & 31;
    int tid = threadIdx.x;
    int lane = tid & 31, wid = tid >> 5;
    int base = c * CH;

    if (tid < 128) {
        Ls[tid]  = g_L [h * SEQ + base + tid];
        dts[tid] = g_dt[h * SEQ + base + tid];
    }
    __syncthreads();

    const float* Gc = g_Gram + (size_t)c * CH * CH;
    for (int idx = tid; idx < 128 * 64; idx += 256) {
        int s = idx >> 6;
        int j2 = (idx & 63) * 2;
        float2 gv = *(const float2*)&Gc[(size_t)s * CH + j2];
        float ls = Ls[s];
        float w0 = (j2 <= s)     ? __expf(ls - Ls[j2])     * dts[j2]     : 0.f;
        float w1 = (j2 + 1 <= s) ? __expf(ls - Ls[j2 + 1]) * dts[j2 + 1] : 0.f;
        float v0 = gv.x * w0, v1 = gv.y * w1;
        float h0 = bf16r(v0), h1 = bf16r(v1);
        int o = s * 68 + (j2 >> 1);
        cs[CO_AMH + o] = packbf2(h0, h1);
        cs[CO_AML + o] = packbf2(v0 - h0, v1 - h1);
    }
    for (int idx = tid; idx < 128 * 16; idx += 256) {
        int j = idx >> 4, p4 = (idx & 15) * 4;
        float4 v = *(const float4*)&g_xbc[(size_t)(base + j) * DCONVIN + h * HD + p4];
        float hx = bf16r(v.x), hy = bf16r(v.y), hz = bf16r(v.z), hw = bf16r(v.w);
        int o = j * 36 + (p4 >> 1);
        cs[CO_XH + o]     = packbf2(hx, hy);
        cs[CO_XH + o + 1] = packbf2(hz, hw);
        cs[CO_XL + o]     = packbf2(v.x - hx, v.y - hy);
        cs[CO_XL + o + 1] = packbf2(v.z - hz, v.w - hw);
    }
    __syncthreads();

    uint32_t sb = (uint32_t)__cvta_generic_to_shared(cs);
    const uint32_t AOFF = ((lane & 15) * 68 + (lane >> 4) * 4) * 4;
    const uint32_t BOFFT = (((lane & 7) + ((lane >> 3) & 1) * 8) * 36 + (lane >> 4) * 4) * 4;

    float acc[8][2][4];
    if (wid < 4) {
#pragma unroll
        for (int mt = 0; mt < 8; mt++)
#pragma unroll
            for (int nt = 0; nt < 2; nt++)
#pragma unroll
                for (int e = 0; e < 4; e++) acc[mt][nt][e] = 0.f;

        for (int ks = 0; ks < 8; ks++) {
            uint32_t bh[2][2], bl[2][2];
            uint32_t nbase = sb + (uint32_t)((ks * 16 * 36) * 4) + (uint32_t)((wid * 16) * 2) + BOFFT;
            ldsm4t(bh[0][0], bh[0][1], bh[1][0], bh[1][1], nbase + CO_XH * 4);
            ldsm4t(bl[0][0], bl[0][1], bl[1][0], bl[1][1], nbase + CO_XL * 4);
#pragma unroll
            for (int mt = 0; mt < 8; mt++) {
                uint32_t abase = sb + (uint32_t)((mt * 16 * 68) * 4) + (uint32_t)((ks * 8) * 4) + AOFF;
                uint32_t ah[4], al[4];
                ldsm4(ah[0], ah[1], ah[2], ah[3], abase + CO_AMH * 4);
                ldsm4(al[0], al[1], al[2], al[3], abase + CO_AML * 4);
#pragma unroll
                for (int nt = 0; nt < 2; nt++) MMA_BF16(acc[mt][nt], ah, bh[nt]);
#pragma unroll
                for (int nt = 0; nt < 2; nt++) MMA_BF16(acc[mt][nt], ah, bl[nt]);
#pragma unroll
                for (int nt = 0; nt < 2; nt++) MMA_BF16(acc[mt][nt], al, bh[nt]);
            }
        }
    }
    __syncthreads();

    if (wid < 4) {
        int g = lane >> 2, tig = lane & 3;
#pragma unroll
        for (int mt = 0; mt < 8; mt++) {
            int s0 = mt * 16 + g;
#pragma unroll
            for (int nt = 0; nt < 2; nt++) {
                int p = wid * 16 + nt * 8 + tig * 2;
                *(float2*)&Yst[s0 * 68 + p]       = make_float2(acc[mt][nt][0], acc[mt][nt][1]);
                *(float2*)&Yst[(s0 + 8) * 68 + p] = make_float2(acc[mt][nt][2], acc[mt][nt][3]);
            }
        }
    }
    __syncthreads();

    float Dh = Dvec[h];
    for (int idx = tid; idx < 128 * 16; idx += 256) {
        int s = idx >> 4, p4 = (idx & 15) * 4;
        int trow = base + s;
        float es = expf(Ls[s]);
        float4 yv = *(float4*)&Yst[s * 68 + p4];
        float4 xv = *(const float4*)&g_xbc[(size_t)trow * DCONVIN + h * HD + p4];
        float4 iv = *(const float4*)&g_Inter[((size_t)(c * CH + s)) * DINNER + h * HD + p4];
        float4 ov;
        ov.x = yv.x + es * iv.x + Dh * xv.x;
        ov.y = yv.y + es * iv.y + Dh * xv.y;
        ov.z = yv.z + es * iv.z + Dh * xv.z;
        ov.w = yv.w + es * iv.w + Dh * xv.w;
        *(float4*)&g_Y[(size_t)trow * DINNER + h * HD + p4] = ov;
    }
}

// ---------------- RMSNorm + SiLU gate -> split bf16 ---------------------------
__global__ void normgate_kernel(const float* __restrict__ nw, const float* __restrict__ nb)
{
    int t = blockIdx.x;
    int tid = threadIdx.x;
    __shared__ float red[256];
    float ss = 0.f;
    for (int d = tid; d < DINNER; d += 256) {
        float v = g_Y[(size_t)t * DINNER + d];
        ss += v * v;
    }
    red[tid] = ss;
    __syncthreads();
    for (int off = 128; off > 0; off >>= 1) {
        if (tid < off) red[tid] += red[tid + off];
        __syncthreads();
    }
    float inv = rsqrtf(red[0] / (float)DINNER + 1e-6f);
    for (int d = tid * 2; d < DINNER; d += 512) {
        float v0 = g_Y[(size_t)t * DINNER + d];
        float v1 = g_Y[(size_t)t * DINNER + d + 1];
        float g0 = v0 * inv * nw[d] + nb[d];
        float g1 = v1 * inv * nw[d + 1] + nb[d + 1];
        float z0 = g_zx[(size_t)t * DPROJ + d];
        float z1 = g_zx[(size_t)t * DPROJ + d + 1];
        g0 *= z0 / (1.f + expf(-z0));
        g1 *= z1 / (1.f + expf(-z1));
        float h0 = bf16r(g0), h1 = bf16r(g1);
        size_t pi = ((size_t)t * DINNER + d) >> 1;
        g_Ghi[pi] = packbf2(h0, h1);
        g_Glo[pi] = packbf2(g0 - h0, g1 - h1);
    }
}

// ---------------- launch ------------------------------------------------------
extern "C" void kernel_launch(void* const* d_in, const int* in_sizes, int n_in,
                              void* d_out, int out_size)
{
    const float* u       = (const float*)d_in[0];
    const float* W_in    = (const float*)d_in[1];
    const float* conv_w  = (const float*)d_in[2];
    const float* conv_b  = (const float*)d_in[3];
    const float* W_out   = (const float*)d_in[4];
    const float* norm_w  = (const float*)d_in[5];
    const float* norm_b  = (const float*)d_in[6];
    const float* dt_bias = (const float*)d_in[7];
    const float* A_log   = (const float*)d_in[8];
    const float* Dv      = (const float*)d_in[9];
    float* out = (float*)d_out;

    float *zx, *Inter;
    uint32_t *u16, *Whi, *Wlo, *Vhi, *Vlo, *Ghi, *Glo, *Hhi, *Hlo, *Chi, *Clo;
    cudaGetSymbolAddress((void**)&zx,   g_zx);
    cudaGetSymbolAddress((void**)&Inter,g_Inter);
    cudaGetSymbolAddress((void**)&u16,  g_u16);
    cudaGetSymbolAddress((void**)&Whi,  g_Whi);
    cudaGetSymbolAddress((void**)&Wlo,  g_Wlo);
    cudaGetSymbolAddress((void**)&Vhi,  g_Vhi);
    cudaGetSymbolAddress((void**)&Vlo,  g_Vlo);
    cudaGetSymbolAddress((void**)&Ghi,  g_Ghi);
    cudaGetSymbolAddress((void**)&Glo,  g_Glo);
    cudaGetSymbolAddress((void**)&Hhi,  g_Hhi);
    cudaGetSymbolAddress((void**)&Hlo,  g_Hlo);
    cudaGetSymbolAddress((void**)&Chi,  g_Chi16);
    cudaGetSymbolAddress((void**)&Clo,  g_Clo16);

    const int SM1 = 3 * 4 * 8192;   // gemm<0,0,4,1>: 3 planes x 4 stages x 8KB
    const int SM2 = 4 * 3 * 8192;   // gemm<1,*,3>:   4 planes x 3 stages x 8KB
    const int SMC = CS_SMEM_U32 * 4;
    const int SMO = CO_SMEM_U32 * 4;
    cudaFuncSetAttribute(gemm_bf16s_kernel<0, 0, 4, 1>, cudaFuncAttributeMaxDynamicSharedMemorySize, SM1);
    cudaFuncSetAttribute(gemm_bf16s_kernel<1, 0, 3>, cudaFuncAttributeMaxDynamicSharedMemorySize, SM2);
    cudaFuncSetAttribute(gemm_bf16s_kernel<1, 1, 3>, cudaFuncAttributeMaxDynamicSharedMemorySize, SM2);
    cudaFuncSetAttribute(chunkstate_mma_kernel, cudaFuncAttributeMaxDynamicSharedMemorySize, SMC);
    cudaFuncSetAttribute(chunkout_mma_kernel, cudaFuncAttributeMaxDynamicSharedMemorySize, SMO);

    // 0. fused operand pre-conversion (u round + W_in/W_out splits)
    convert_all_kernel<<<(NP_U + NP_W + NP_V + 255) / 256, 256>>>(u, W_in, W_out);
    // 1. in_proj GEMM (4-stage, 2-tiles-per-barrier, 2 mma)
    gemm_bf16s_kernel<0, 0, 4, 1><<<dim3((DPROJ + 127) / 128, SEQ / 128), 256, SM1>>>(
        u16, nullptr, Whi, Wlo, zx, SEQ, DPROJ, DMODEL);
    // 2. causal depthwise conv + silu (+ fused C split)
    conv_silu_kernel<<<dim3((DCONVIN + 255) / 256, SEQ / 8), 256>>>(conv_w, conv_b);
    // 3. dt softplus + per-chunk cumsum
    dtscan_kernel<<<NCH * NH, CH>>>(dt_bias, A_log);
    // 3b. gram matrices
    gram_kernel<<<NCH, 256>>>();
    // 4. chunk-local states (mma.sync TC)
    chunkstate_mma_kernel<<<NCH * NH, 128, SMC>>>();
    // 5. inter-chunk scan
    scan_kernel<<<(NH * HD * (DSTATE / 2)) / 256, 256>>>();
    // 5b. inter term (batched, 3-stage single-sync)
    gemm_bf16s_kernel<1, 1, 3><<<dim3(DINNER / 128, 1, NCH), 256, SM2>>>(
        Chi, Clo, Hhi, Hlo, Inter, CH, DINNER, DSTATE);
    // 6. per-chunk output
    chunkout_mma_kernel<<<NCH * NH, 256, SMO>>>(Dv);
    // 7. RMSNorm + gate
    normgate_kernel<<<SEQ, 256>>>(norm_w, norm_b);
    // 8. out_proj GEMM (3-stage single-sync, 3 mma)
    gemm_bf16s_kernel<1, 0, 3><<<dim3(DMODEL / 128, SEQ / 128), 256, SM2>>>(
        Ghi, Glo, Vhi, Vlo, out, SEQ, DMODEL, DINNER);
}

// round 17
// speedup vs baseline: 1.2888x; 1.0380x over previous
#include <cuda_runtime.h>
#include <cuda_bf16.h>
#include <cstdint>

#define SEQ     4096
#define DMODEL  1024
#define DPROJ   4384
#define DINNER  2048
#define DCONVIN 2304
#define DSTATE  128
#define NH      32
#define HD      64
#define NCH     32
#define CH      128

// ---------------- scratch (static __device__, allocation-free) ----------------
__device__ float g_zx [SEQ * DPROJ];
__device__ float g_xbc[SEQ * DCONVIN];
__device__ float g_dt [NH * SEQ];
__device__ float g_L  [NH * SEQ];
__device__ float g_S  [NCH * NH * HD * DSTATE];
__device__ float g_Y  [SEQ * DINNER];
__device__ float g_Gram[NCH * CH * CH];
__device__ float g_Inter[NCH * CH * DINNER];

__device__ uint32_t g_u16[SEQ * DMODEL / 2];
__device__ uint32_t g_Whi[DPROJ * DMODEL / 2];
__device__ uint32_t g_Wlo[DPROJ * DMODEL / 2];
__device__ uint32_t g_Vhi[DMODEL * DINNER / 2];
__device__ uint32_t g_Vlo[DMODEL * DINNER / 2];
__device__ uint32_t g_Ghi[SEQ * DINNER / 2];
__device__ uint32_t g_Glo[SEQ * DINNER / 2];
__device__ uint32_t g_Hhi[NCH * DINNER * DSTATE / 2];
__device__ uint32_t g_Hlo[NCH * DINNER * DSTATE / 2];
__device__ __nv_bfloat16 g_Chi16[SEQ * DSTATE];
__device__ __nv_bfloat16 g_Clo16[SEQ * DSTATE];

__device__ __forceinline__ float bf16r(float x) {
    return __bfloat162float(__float2bfloat16(x));
}
__device__ __forceinline__ uint32_t packbf2(float x, float y) {
    __nv_bfloat162 t = __floats2bfloat162_rn(x, y);
    return *(uint32_t*)&t;
}
__device__ __forceinline__ void cp16(void* sdst, const void* gsrc, int sz) {
    uint32_t sa = (uint32_t)__cvta_generic_to_shared(sdst);
    asm volatile("cp.async.cg.shared.global [%0], [%1], 16, %2;" :: "r"(sa), "l"(gsrc), "r"(sz));
}
__device__ __forceinline__ void ldsm4(uint32_t& r0, uint32_t& r1, uint32_t& r2, uint32_t& r3,
                                      uint32_t saddr) {
    asm volatile("ldmatrix.sync.aligned.m8n8.x4.shared.b16 {%0,%1,%2,%3}, [%4];"
                 : "=r"(r0), "=r"(r1), "=r"(r2), "=r"(r3) : "r"(saddr));
}
__device__ __forceinline__ void ldsm4t(uint32_t& r0, uint32_t& r1, uint32_t& r2, uint32_t& r3,
                                       uint32_t saddr) {
    asm volatile("ldmatrix.sync.aligned.m8n8.x4.trans.shared.b16 {%0,%1,%2,%3}, [%4];"
                 : "=r"(r0), "=r"(r1), "=r"(r2), "=r"(r3) : "r"(saddr));
}

#define MMA_BF16(d, a, b)                                                        \
    asm volatile("mma.sync.aligned.m16n8k16.row.col.f32.bf16.bf16.f32 "          \
                 "{%0,%1,%2,%3}, {%4,%5,%6,%7}, {%8,%9}, {%0,%1,%2,%3};"         \
                 : "+f"(d[0]), "+f"(d[1]), "+f"(d[2]), "+f"(d[3])                \
                 : "r"(a[0]), "r"(a[1]), "r"(a[2]), "r"(a[3]),                   \
                   "r"(b[0]), "r"(b[1]))

// ---------------- operand conversion ------------------------------------------
#define NP_U (SEQ * DMODEL / 2)
#define NP_W (DPROJ * DMODEL / 2)
#define NP_V (DMODEL * DINNER / 2)
__global__ void convert_uW_kernel(const float* __restrict__ u, const float* __restrict__ W_in)
{
    int i = blockIdx.x * 256 + threadIdx.x;
    if (i < NP_U) {
        float2 v = *(const float2*)(u + (size_t)i * 2);
        g_u16[i] = packbf2(v.x, v.y);
    } else if (i < NP_U + NP_W) {
        int j = i - NP_U;
        float2 v = *(const float2*)(W_in + (size_t)j * 2);
        float hx = bf16r(v.x), hy = bf16r(v.y);
        g_Whi[j] = packbf2(hx, hy);
        g_Wlo[j] = packbf2(v.x - hx, v.y - hy);
    }
}
__global__ void convert_V_kernel(const float* __restrict__ W_out)
{
    int j = blockIdx.x * 256 + threadIdx.x;
    if (j >= NP_V) return;
    float2 v = *(const float2*)(W_out + (size_t)j * 2);
    float hx = bf16r(v.x), hy = bf16r(v.y);
    g_Vhi[j] = packbf2(hx, hy);
    g_Vlo[j] = packbf2(v.x - hx, v.y - hy);
}

// ---------------- tensor-core NT GEMM, swizzled smem, pipelined ---------------
template<int HAS_ALO, int CHUNKZ, int STAGES, int TWO_TILE = 0>
__global__ void __launch_bounds__(256) gemm_bf16s_kernel(
    const uint32_t* __restrict__ Ahi_g, const uint32_t* __restrict__ Alo_g,
    const uint32_t* __restrict__ Bhi_g, const uint32_t* __restrict__ Blo_g,
    float* __restrict__ C, int M, int N, int K)
{
    extern __shared__ uint32_t smemu[];
    const uint32_t PS    = STAGES * 2048;
    const uint32_t BHS_O = PS * (1 + (HAS_ALO ? 1 : 0));
    const uint32_t BLS_O = BHS_O + PS;
    uint32_t* Ahs = smemu;
    uint32_t* Als = smemu + PS;
    uint32_t* Bhs = smemu + BHS_O;
    uint32_t* Bls = smemu + BLS_O;

    if (CHUNKZ) {
        size_t cz = blockIdx.z;
        Ahi_g += cz * (size_t)CH * (DSTATE / 2);
        if (HAS_ALO) Alo_g += cz * (size_t)CH * (DSTATE / 2);
        Bhi_g += cz * (size_t)DINNER * (DSTATE / 2);
        Blo_g += cz * (size_t)DINNER * (DSTATE / 2);
        C     += cz * (size_t)CH * DINNER;
    }

    const int K2 = K >> 1;
    const int KT = K2 >> 4;
    const int bn = blockIdx.x * 128;
    const int bm = blockIdx.y * 128;
    const int tid = threadIdx.x;
    const int lane = tid & 31;
    const int wid = tid >> 5;
    const int warpM = wid >> 2;
    const int warpN = wid & 3;
    const int g = lane >> 2;
    const int tig = lane & 3;

    const uint32_t sb32 = (uint32_t)__cvta_generic_to_shared(smemu);
    const int arow = (lane & 15);
    const int abit = lane >> 4;
    const int brow = (lane & 7) + ((lane >> 4) << 3);
    const int bbit = (lane >> 3) & 1;

    auto issue = [&](int kt) {
        int k0u = kt * 16;
        uint32_t so = (uint32_t)((kt % STAGES) * 2048);
#pragma unroll
        for (int r = 0; r < 2; r++) {
            int idx = r * 256 + tid;
            int row = idx >> 2;
            int b = idx & 3;
            uint32_t dsto = so + row * 16 + ((b ^ ((row >> 1) & 3)) << 2);
            size_t ga = (size_t)(bm + row) * K2 + k0u + b * 4;
            cp16(&Ahs[dsto], Ahi_g + ga, 16);
            if (HAS_ALO) cp16(&Als[dsto], Alo_g + ga, 16);
            int nn = bn + row;
            int sz = (nn < N) ? 16 : 0;
            size_t gb = (size_t)((nn < N) ? nn : 0) * K2 + k0u + b * 4;
            cp16(&Bhs[dsto], Bhi_g + gb, sz);
            cp16(&Bls[dsto], Blo_g + gb, sz);
        }
        asm volatile("cp.async.commit_group;" ::: "memory");
    };

    float acc[4][4][4];
#pragma unroll
    for (int mt = 0; mt < 4; mt++)
#pragma unroll
        for (int nt = 0; nt < 4; nt++)
#pragma unroll
            for (int e = 0; e < 4; e++) acc[mt][nt][e] = 0.f;

    auto compute = [&](int kt) {
        const uint32_t so4 = (uint32_t)((kt % STAGES) * 2048) * 4;
#pragma unroll
        for (int kh = 0; kh < 2; kh++) {
            uint32_t bhi[4][2], blo[4][2];
#pragma unroll
            for (int ntp = 0; ntp < 2; ntp++) {
                int row = warpN * 32 + ntp * 16 + brow;
                int b = kh * 2 + bbit;
                uint32_t off = so4 + row * 64 + ((b ^ ((row >> 1) & 3)) << 4);
                ldsm4(bhi[ntp * 2][0], bhi[ntp * 2][1], bhi[ntp * 2 + 1][0], bhi[ntp * 2 + 1][1],
                      sb32 + BHS_O * 4 + off);
                ldsm4(blo[ntp * 2][0], blo[ntp * 2][1], blo[ntp * 2 + 1][0], blo[ntp * 2 + 1][1],
                      sb32 + BLS_O * 4 + off);
            }
#pragma unroll
            for (int mt = 0; mt < 4; mt++) {
                int row = warpM * 64 + mt * 16 + arow;
                int b = kh * 2 + abit;
                uint32_t off = so4 + row * 64 + ((b ^ ((row >> 1) & 3)) << 4);
                uint32_t ah[4], al[4];
                ldsm4(ah[0], ah[1], ah[2], ah[3], sb32 + off);
                if (HAS_ALO) ldsm4(al[0], al[1], al[2], al[3], sb32 + PS * 4 + off);
#pragma unroll
                for (int nt = 0; nt < 4; nt++) MMA_BF16(acc[mt][nt], ah, bhi[nt]);
#pragma unroll
                for (int nt = 0; nt < 4; nt++) MMA_BF16(acc[mt][nt], ah, blo[nt]);
                if (HAS_ALO) {
#pragma unroll
                    for (int nt = 0; nt < 4; nt++) MMA_BF16(acc[mt][nt], al, bhi[nt]);
                }
            }
        }
    };

    if (TWO_TILE) {
        issue(0);
        issue(1);
        for (int kt = 0; kt < KT; kt += 2) {
            asm volatile("cp.async.wait_group 0;" ::: "memory");
            __syncthreads();
            if (kt + 2 < KT) { issue(kt + 2); issue(kt + 3); }
            compute(kt);
            compute(kt + 1);
        }
    } else {
#pragma unroll
        for (int s = 0; s < STAGES - 1; s++)
            if (s < KT) issue(s);

        for (int kt = 0; kt < KT; kt++) {
            int rem = KT - 1 - kt;
            if (rem >= STAGES - 2) {
                if (STAGES - 2 == 2) asm volatile("cp.async.wait_group 2;" ::: "memory");
                else                 asm volatile("cp.async.wait_group 1;" ::: "memory");
            } else if (rem == 1) {
                asm volatile("cp.async.wait_group 1;" ::: "memory");
            } else {
                asm volatile("cp.async.wait_group 0;" ::: "memory");
            }
            __syncthreads();
            compute(kt);
            if (kt + STAGES - 1 < KT) issue(kt + STAGES - 1);
        }
    }

#pragma unroll
    for (int mt = 0; mt < 4; mt++) {
        int row = bm + warpM * 64 + mt * 16 + g;
#pragma unroll
        for (int nt = 0; nt < 4; nt++) {
            int col = bn + warpN * 32 + nt * 8 + tig * 2;
            if (col < N) {
                C[(size_t)row * N + col]           = acc[mt][nt][0];
                C[(size_t)row * N + col + 1]       = acc[mt][nt][1];
                C[(size_t)(row + 8) * N + col]     = acc[mt][nt][2];
                C[(size_t)(row + 8) * N + col + 1] = acc[mt][nt][3];
            }
        }
    }
}

// ---------------- causal depthwise conv(4) + SiLU + fused C split -------------
__global__ void conv_silu_kernel(const float* __restrict__ cw, const float* __restrict__ cb)
{
    int c = blockIdx.x * 256 + threadIdx.x;
    if (c >= DCONVIN) return;
    int t0 = blockIdx.y * 8;
    float w0 = cw[c * 4], w1 = cw[c * 4 + 1], w2 = cw[c * 4 + 2], w3 = cw[c * 4 + 3];
    float bias = cb[c];
    float v[11];
#pragma unroll
    for (int i = 0; i < 11; i++) {
        int tt = t0 - 3 + i;
        v[i] = (tt >= 0) ? g_zx[(size_t)tt * DPROJ + DINNER + c] : 0.f;
    }
    bool isC = (c >= DINNER + DSTATE);
    int n = c - (DINNER + DSTATE);
#pragma unroll
    for (int i = 0; i < 8; i++) {
        float s = bias + v[i] * w0 + v[i + 1] * w1 + v[i + 2] * w2 + v[i + 3] * w3;
        float a = s / (1.f + expf(-s));
        g_xbc[(size_t)(t0 + i) * DCONVIN + c] = a;
        if (isC) {
            float hi = bf16r(a);
            g_Chi16[(size_t)(t0 + i) * DSTATE + n] = __float2bfloat16(hi);
            g_Clo16[(size_t)(t0 + i) * DSTATE + n] = __float2bfloat16(a - hi);
        }
    }
}

// ---------------- softplus(dt)+dt_bias, dt*A, per-chunk inclusive cumsum ------
__global__ void dtscan_kernel(const float* __restrict__ dt_bias, const float* __restrict__ A_log)
{
    int bid = blockIdx.x;
    int c = bid >> 5, h = bid & 31;
    int s = threadIdx.x;
    int t = c * CH + s;
    float raw = g_zx[(size_t)t * DPROJ + (DINNER + DINNER + 2 * DSTATE) + h] + dt_bias[h];
    float dtv = (raw > 20.f) ? raw : log1pf(expf(raw));
    float Ah = -expf(A_log[h]);
    __shared__ float sm[CH];
    sm[s] = dtv * Ah;
    g_dt[h * SEQ + t] = dtv;
    __syncthreads();
    for (int off = 1; off < CH; off <<= 1) {
        float add = (s >= off) ? sm[s - off] : 0.f;
        __syncthreads();
        sm[s] += add;
        __syncthreads();
    }
    g_L[h * SEQ + t] = sm[s];
}

// ---------------- gram: G[c][s][j] = C_s . B_j --------------------------------
__global__ void __launch_bounds__(256) gram_kernel()
{
    int c = blockIdx.x;
    __shared__ float CsT[16 * 132];
    __shared__ float BsT[16 * 132];
    int tid = threadIdx.x;
    int ts = tid >> 4, tj = tid & 15;
    int base = c * CH;

    float acc[8][8];
#pragma unroll
    for (int i = 0; i < 8; i++)
#pragma unroll
        for (int k = 0; k < 8; k++) acc[i][k] = 0.f;

    for (int n0 = 0; n0 < DSTATE; n0 += 16) {
#pragma unroll
        for (int r = 0; r < 2; r++) {
            int qi = r * 256 + tid;
            int s = qi >> 2, nq = qi & 3;
            float4 vc = *(const float4*)&g_xbc[(size_t)(base + s) * DCONVIN + DINNER + DSTATE + n0 + nq * 4];
            CsT[(nq * 4 + 0) * 132 + s] = vc.x; CsT[(nq * 4 + 1) * 132 + s] = vc.y;
            CsT[(nq * 4 + 2) * 132 + s] = vc.z; CsT[(nq * 4 + 3) * 132 + s] = vc.w;
            float4 vb = *(const float4*)&g_xbc[(size_t)(base + s) * DCONVIN + DINNER + n0 + nq * 4];
            BsT[(nq * 4 + 0) * 132 + s] = vb.x; BsT[(nq * 4 + 1) * 132 + s] = vb.y;
            BsT[(nq * 4 + 2) * 132 + s] = vb.z; BsT[(nq * 4 + 3) * 132 + s] = vb.w;
        }
        __syncthreads();
#pragma unroll
        for (int nn = 0; nn < 16; nn++) {
            float4 c0 = *(float4*)&CsT[nn * 132 + ts * 8];
            float4 c1 = *(float4*)&CsT[nn * 132 + ts * 8 + 4];
            float4 b0 = *(float4*)&BsT[nn * 132 + tj * 8];
            float4 b1 = *(float4*)&BsT[nn * 132 + tj * 8 + 4];
            float cv[8] = {c0.x, c0.y, c0.z, c0.w, c1.x, c1.y, c1.z, c1.w};
            float bv[8] = {b0.x, b0.y, b0.z, b0.w, b1.x, b1.y, b1.z, b1.w};
#pragma unroll
            for (int i = 0; i < 8; i++)
#pragma unroll
                for (int k = 0; k < 8; k++) acc[i][k] += cv[i] * bv[k];
        }
        __syncthreads();
    }
#pragma unroll
    for (int i = 0; i < 8; i++) {
        size_t row = (size_t)(c * CH + ts * 8 + i) * CH;
        *(float4*)&g_Gram[row + tj * 8]     = make_float4(acc[i][0], acc[i][1], acc[i][2], acc[i][3]);
        *(float4*)&g_Gram[row + tj * 8 + 4] = make_float4(acc[i][4], acc[i][5], acc[i][6], acc[i][7]);
    }
}

// ---------------- pass 1 (tensor cores): S[c,h] = (w.X)^T @ B -----------------
#define CS_AH 0
#define CS_AL (128 * 36)
#define CS_BH (2 * 128 * 36)
#define CS_BL (CS_BH + 128 * 68)
#define CS_W  (CS_BL + 128 * 68)
#define CS_SMEM_U32 (CS_W + 128)
__global__ void __launch_bounds__(256) chunkstate_mma_kernel()
{
    extern __shared__ uint32_t cs[];
    float* ws = (float*)(cs + CS_W);
    int bid = blockIdx.x;
    int c = bid >> 5, h = bid & 31;
    int tid = threadIdx.x;
    int lane = tid & 31, wid = tid >> 5;
    int base = c * CH;

    if (tid < 128) {
        float Lend = g_L[h * SEQ + base + CH - 1];
        ws[tid] = __expf(Lend - g_L[h * SEQ + base + tid]) * g_dt[h * SEQ + base + tid];
    }
    __syncthreads();

    for (int idx = tid; idx < 128 * 16; idx += 256) {
        int j = idx >> 4, p4 = (idx & 15) * 4;
        float4 v = *(const float4*)&g_xbc[(size_t)(base + j) * DCONVIN + h * HD + p4];
        float w = ws[j];
        v.x *= w; v.y *= w; v.z *= w; v.w *= w;
        float hx = bf16r(v.x), hy = bf16r(v.y), hz = bf16r(v.z), hw = bf16r(v.w);
        int o = j * 36 + (p4 >> 1);
        cs[CS_AH + o]     = packbf2(hx, hy);
        cs[CS_AH + o + 1] = packbf2(hz, hw);
        cs[CS_AL + o]     = packbf2(v.x - hx, v.y - hy);
        cs[CS_AL + o + 1] = packbf2(v.z - hz, v.w - hw);
    }
    for (int idx = tid; idx < 128 * 32; idx += 256) {
        int j = idx >> 5, n4 = (idx & 31) * 4;
        float4 v = *(const float4*)&g_xbc[(size_t)(base + j) * DCONVIN + DINNER + n4];
        float hx = bf16r(v.x), hy = bf16r(v.y), hz = bf16r(v.z), hw = bf16r(v.w);
        int o = j * 68 + (n4 >> 1);
        cs[CS_BH + o]     = packbf2(hx, hy);
        cs[CS_BH + o + 1] = packbf2(hz, hw);
        cs[CS_BL + o]     = packbf2(v.x - hx, v.y - hy);
        cs[CS_BL + o + 1] = packbf2(v.z - hz, v.w - hw);
    }
    __syncthreads();

    if (wid < 4) {
        uint32_t sb = (uint32_t)__cvta_generic_to_shared(cs);
        const uint32_t AOFFT = (((lane & 7) + (lane >> 4) * 8) * 36 + ((lane >> 3) & 1) * 4) * 4;
        const uint32_t BOFFT = (((lane & 7) + ((lane >> 3) & 1) * 8) * 68 + (lane >> 4) * 4) * 4;

        float acc[4][4][4];
#pragma unroll
        for (int mt = 0; mt < 4; mt++)
#pragma unroll
            for (int nt = 0; nt < 4; nt++)
#pragma unroll
                for (int e = 0; e < 4; e++) acc[mt][nt][e] = 0.f;

        for (int ks = 0; ks < 8; ks++) {
            uint32_t bh[4][2], bl[4][2];
#pragma unroll
            for (int np = 0; np < 2; np++) {
                uint32_t nbase = sb + (uint32_t)((ks * 16 * 68) * 4) + (uint32_t)((wid * 32 + np * 16) * 2) + BOFFT;
                ldsm4t(bh[np * 2][0], bh[np * 2][1], bh[np * 2 + 1][0], bh[np * 2 + 1][1],
                       nbase + CS_BH * 4);
                ldsm4t(bl[np * 2][0], bl[np * 2][1], bl[np * 2 + 1][0], bl[np * 2 + 1][1],
                       nbase + CS_BL * 4);
            }
#pragma unroll
            for (int mt = 0; mt < 4; mt++) {
                uint32_t abase = sb + (uint32_t)((ks * 16 * 36) * 4) + (uint32_t)((mt * 16) * 2) + AOFFT;
                uint32_t ah[4], al[4];
                ldsm4t(ah[0], ah[1], ah[2], ah[3], abase + CS_AH * 4);
                ldsm4t(al[0], al[1], al[2], al[3], abase + CS_AL * 4);
#pragma unroll
                for (int nt = 0; nt < 4; nt++) MMA_BF16(acc[mt][nt], ah, bh[nt]);
#pragma unroll
                for (int nt = 0; nt < 4; nt++) MMA_BF16(acc[mt][nt], ah, bl[nt]);
#pragma unroll
                for (int nt = 0; nt < 4; nt++) MMA_BF16(acc[mt][nt], al, bh[nt]);
            }
        }

        int g = lane >> 2, tig = lane & 3;
#pragma unroll
        for (int mt = 0; mt < 4; mt++) {
            int p = mt * 16 + g;
#pragma unroll
            for (int nt = 0; nt < 4; nt++) {
                int n = wid * 32 + nt * 8 + tig * 2;
                size_t row = ((size_t)(c * NH + h) * HD + p) * DSTATE;
                g_S[row + n]     = acc[mt][nt][0];
                g_S[row + n + 1] = acc[mt][nt][1];
                g_S[row + 8 * DSTATE + n]     = acc[mt][nt][2];
                g_S[row + 8 * DSTATE + n + 1] = acc[mt][nt][3];
            }
        }
    }
}

// ---------------- pass 2: 32-step scan; emit H as split bf16 ------------------
__global__ void scan_kernel()
{
    int idx = blockIdx.x * 256 + threadIdx.x;
    int h = idx >> 12;
    int rem = idx & 4095;
    int p = rem >> 6;
    int n2 = (rem & 63) * 2;
    float h0 = 0.f, h1 = 0.f;
    for (int c = 0; c < NCH; c++) {
        size_t row = (size_t)c * DINNER + h * HD + p;
        float b0 = bf16r(h0), b1 = bf16r(h1);
        g_Hhi[row * 64 + (n2 >> 1)] = packbf2(b0, b1);
        g_Hlo[row * 64 + (n2 >> 1)] = packbf2(h0 - b0, h1 - b1);
        float2 s = *(const float2*)&g_S[((size_t)(c * NH + h) * HD + p) * DSTATE + n2];
        float dA = expf(g_L[h * SEQ + c * CH + CH - 1]);
        h0 = dA * h0 + s.x;
        h1 = dA * h1 + s.y;
    }
}

// ---------------- pass 3 (tensor cores + staged epilogue) ---------------------
#define CO_AMH 0
#define CO_AML (128 * 68)
#define CO_XH  (2 * 128 * 68)
#define CO_XL  (CO_XH + 128 * 36)
#define CO_LS  (CO_XL + 128 * 36)
#define CO_DTS (CO_LS + 128)
#define CO_SMEM_U32 (CO_DTS + 128)
__global__ void __launch_bounds__(256) chunkout_mma_kernel(const float* __restrict__ Dvec)
{
    extern __shared__ uint32_t cs[];
    float* Ls  = (float*)(cs + CO_LS);
    float* dts = (float*)(cs + CO_DTS);
    float* Yst = (float*)cs;
    int bid = blockIdx.x;
    int c = bid >> 5, h = bid & 31;
    int tid = threadIdx.x;
    int lane = tid & 31, wid = tid >> 5;
    int base = c * CH;

    if (tid < 128) {
        Ls[tid]  = g_L [h * SEQ + base + tid];
        dts[tid] = g_dt[h * SEQ + base + tid];
    }
    __syncthreads();

    const float* Gc = g_Gram + (size_t)c * CH * CH;
    for (int idx = tid; idx < 128 * 64; idx += 256) {
        int s = idx >> 6;
        int j2 = (idx & 63) * 2;
        float2 gv = *(const float2*)&Gc[(size_t)s * CH + j2];
        float ls = Ls[s];
        float w0 = (j2 <= s)     ? __expf(ls - Ls[j2])     * dts[j2]     : 0.f;
        float w1 = (j2 + 1 <= s) ? __expf(ls - Ls[j2 + 1]) * dts[j2 + 1] : 0.f;
        float v0 = gv.x * w0, v1 = gv.y * w1;
        float h0 = bf16r(v0), h1 = bf16r(v1);
        int o = s * 68 + (j2 >> 1);
        cs[CO_AMH + o] = packbf2(h0, h1);
        cs[CO_AML + o] = packbf2(v0 - h0, v1 - h1);
    }
    for (int idx = tid; idx < 128 * 16; idx += 256) {
        int j = idx >> 4, p4 = (idx & 15) * 4;
        float4 v = *(const float4*)&g_xbc[(size_t)(base + j) * DCONVIN + h * HD + p4];
        float hx = bf16r(v.x), hy = bf16r(v.y), hz = bf16r(v.z), hw = bf16r(v.w);
        int o = j * 36 + (p4 >> 1);
        cs[CO_XH + o]     = packbf2(hx, hy);
        cs[CO_XH + o + 1] = packbf2(hz, hw);
        cs[CO_XL + o]     = packbf2(v.x - hx, v.y - hy);
        cs[CO_XL + o + 1] = packbf2(v.z - hz, v.w - hw);
    }
    __syncthreads();

    uint32_t sb = (uint32_t)__cvta_generic_to_shared(cs);
    const uint32_t AOFF = ((lane & 15) * 68 + (lane >> 4) * 4) * 4;
    const uint32_t BOFFT = (((lane & 7) + ((lane >> 3) & 1) * 8) * 36 + (lane >> 4) * 4) * 4;

    float acc[8][2][4];
    if (wid < 4) {
#pragma unroll
        for (int mt = 0; mt < 8; mt++)
#pragma unroll
            for (int nt = 0; nt < 2; nt++)
#pragma unroll
                for (int e = 0; e < 4; e++) acc[mt][nt][e] = 0.f;

        for (int ks = 0; ks < 8; ks++) {
            uint32_t bh[2][2], bl[2][2];
            uint32_t nbase = sb + (uint32_t)((ks * 16 * 36) * 4) + (uint32_t)((wid * 16) * 2) + BOFFT;
            ldsm4t(bh[0][0], bh[0][1], bh[1][0], bh[1][1], nbase + CO_XH * 4);
            ldsm4t(bl[0][0], bl[0][1], bl[1][0], bl[1][1], nbase + CO_XL * 4);
#pragma unroll
            for (int mt = 0; mt < 8; mt++) {
                uint32_t abase = sb + (uint32_t)((mt * 16 * 68) * 4) + (uint32_t)((ks * 8) * 4) + AOFF;
                uint32_t ah[4], al[4];
                ldsm4(ah[0], ah[1], ah[2], ah[3], abase + CO_AMH * 4);
                ldsm4(al[0], al[1], al[2], al[3], abase + CO_AML * 4);
#pragma unroll
                for (int nt = 0; nt < 2; nt++) MMA_BF16(acc[mt][nt], ah, bh[nt]);
#pragma unroll
                for (int nt = 0; nt < 2; nt++) MMA_BF16(acc[mt][nt], ah, bl[nt]);
#pragma unroll
                for (int nt = 0; nt < 2; nt++) MMA_BF16(acc[mt][nt], al, bh[nt]);
            }
        }
    }
    __syncthreads();

    if (wid < 4) {
        int g = lane >> 2, tig = lane & 3;
#pragma unroll
        for (int mt = 0; mt < 8; mt++) {
            int s0 = mt * 16 + g;
#pragma unroll
            for (int nt = 0; nt < 2; nt++) {
                int p = wid * 16 + nt * 8 + tig * 2;
                *(float2*)&Yst[s0 * 68 + p]       = make_float2(acc[mt][nt][0], acc[mt][nt][1]);
                *(float2*)&Yst[(s0 + 8) * 68 + p] = make_float2(acc[mt][nt][2], acc[mt][nt][3]);
            }
        }
    }
    __syncthreads();

    float Dh = Dvec[h];
    for (int idx = tid; idx < 128 * 16; idx += 256) {
        int s = idx >> 4, p4 = (idx & 15) * 4;
        int trow = base + s;
        float es = expf(Ls[s]);
        float4 yv = *(float4*)&Yst[s * 68 + p4];
        float4 xv = *(const float4*)&g_xbc[(size_t)trow * DCONVIN + h * HD + p4];
        float4 iv = *(const float4*)&g_Inter[((size_t)(c * CH + s)) * DINNER + h * HD + p4];
        float4 ov;
        ov.x = yv.x + es * iv.x + Dh * xv.x;
        ov.y = yv.y + es * iv.y + Dh * xv.y;
        ov.z = yv.z + es * iv.z + Dh * xv.z;
        ov.w = yv.w + es * iv.w + Dh * xv.w;
        *(float4*)&g_Y[(size_t)trow * DINNER + h * HD + p4] = ov;
    }
}

// ---------------- RMSNorm + SiLU gate -> split bf16 ---------------------------
__global__ void normgate_kernel(const float* __restrict__ nw, const float* __restrict__ nb)
{
    int t = blockIdx.x;
    int tid = threadIdx.x;
    __shared__ float red[256];
    float ss = 0.f;
    for (int d = tid; d < DINNER; d += 256) {
        float v = g_Y[(size_t)t * DINNER + d];
        ss += v * v;
    }
    red[tid] = ss;
    __syncthreads();
    for (int off = 128; off > 0; off >>= 1) {
        if (tid < off) red[tid] += red[tid + off];
        __syncthreads();
    }
    float inv = rsqrtf(red[0] / (float)DINNER + 1e-6f);
    for (int d = tid * 2; d < DINNER; d += 512) {
        float v0 = g_Y[(size_t)t * DINNER + d];
        float v1 = g_Y[(size_t)t * DINNER + d + 1];
        float g0 = v0 * inv * nw[d] + nb[d];
        float g1 = v1 * inv * nw[d + 1] + nb[d + 1];
        float z0 = g_zx[(size_t)t * DPROJ + d];
        float z1 = g_zx[(size_t)t * DPROJ + d + 1];
        g0 *= z0 / (1.f + expf(-z0));
        g1 *= z1 / (1.f + expf(-z1));
        float h0 = bf16r(g0), h1 = bf16r(g1);
        size_t pi = ((size_t)t * DINNER + d) >> 1;
        g_Ghi[pi] = packbf2(h0, h1);
        g_Glo[pi] = packbf2(g0 - h0, g1 - h1);
    }
}

// ---------------- launch ------------------------------------------------------
extern "C" void kernel_launch(void* const* d_in, const int* in_sizes, int n_in,
                              void* d_out, int out_size)
{
    const float* u       = (const float*)d_in[0];
    const float* W_in    = (const float*)d_in[1];
    const float* conv_w  = (const float*)d_in[2];
    const float* conv_b  = (const float*)d_in[3];
    const float* W_out   = (const float*)d_in[4];
    const float* norm_w  = (const float*)d_in[5];
    const float* norm_b  = (const float*)d_in[6];
    const float* dt_bias = (const float*)d_in[7];
    const float* A_log   = (const float*)d_in[8];
    const float* Dv      = (const float*)d_in[9];
    float* out = (float*)d_out;

    float *zx, *Inter;
    uint32_t *u16, *Whi, *Wlo, *Vhi, *Vlo, *Ghi, *Glo, *Hhi, *Hlo, *Chi, *Clo;
    cudaGetSymbolAddress((void**)&zx,   g_zx);
    cudaGetSymbolAddress((void**)&Inter,g_Inter);
    cudaGetSymbolAddress((void**)&u16,  g_u16);
    cudaGetSymbolAddress((void**)&Whi,  g_Whi);
    cudaGetSymbolAddress((void**)&Wlo,  g_Wlo);
    cudaGetSymbolAddress((void**)&Vhi,  g_Vhi);
    cudaGetSymbolAddress((void**)&Vlo,  g_Vlo);
    cudaGetSymbolAddress((void**)&Ghi,  g_Ghi);
    cudaGetSymbolAddress((void**)&Glo,  g_Glo);
    cudaGetSymbolAddress((void**)&Hhi,  g_Hhi);
    cudaGetSymbolAddress((void**)&Hlo,  g_Hlo);
    cudaGetSymbolAddress((void**)&Chi,  g_Chi16);
    cudaGetSymbolAddress((void**)&Clo,  g_Clo16);

    // streams/events created once (outside graph capture on the first call)
    static cudaStream_t s2 = nullptr;
    static cudaEvent_t evA = nullptr, evConv = nullptr, evDt = nullptr, evGram = nullptr, evV = nullptr;
    if (!s2) {
        cudaStreamCreateWithFlags(&s2, cudaStreamNonBlocking);
        cudaEventCreateWithFlags(&evA,    cudaEventDisableTiming);
        cudaEventCreateWithFlags(&evConv, cudaEventDisableTiming);
        cudaEventCreateWithFlags(&evDt,   cudaEventDisableTiming);
        cudaEventCreateWithFlags(&evGram, cudaEventDisableTiming);
        cudaEventCreateWithFlags(&evV,    cudaEventDisableTiming);
    }

    const int SM1 = 3 * 4 * 8192;
    const int SM2 = 4 * 3 * 8192;
    const int SMC = CS_SMEM_U32 * 4;
    const int SMO = CO_SMEM_U32 * 4;
    cudaFuncSetAttribute(gemm_bf16s_kernel<0, 0, 4, 1>, cudaFuncAttributeMaxDynamicSharedMemorySize, SM1);
    cudaFuncSetAttribute(gemm_bf16s_kernel<1, 0, 3>, cudaFuncAttributeMaxDynamicSharedMemorySize, SM2);
    cudaFuncSetAttribute(gemm_bf16s_kernel<1, 1, 3>, cudaFuncAttributeMaxDynamicSharedMemorySize, SM2);
    cudaFuncSetAttribute(chunkstate_mma_kernel, cudaFuncAttributeMaxDynamicSharedMemorySize, SMC);
    cudaFuncSetAttribute(chunkout_mma_kernel, cudaFuncAttributeMaxDynamicSharedMemorySize, SMO);

    // fork: W_out conversion on s2 (needed only by final GEMM)
    cudaEventRecord(evA, 0);                 // origin-stream fork point
    cudaStreamWaitEvent(s2, evA, 0);
    convert_V_kernel<<<(NP_V + 255) / 256, 256, 0, s2>>>(W_out);
    cudaEventRecord(evV, s2);

    // 0. u + W_in conversion (needed by GEMM1)
    convert_uW_kernel<<<(NP_U + NP_W + 255) / 256, 256>>>(u, W_in);
    // 1. in_proj GEMM
    gemm_bf16s_kernel<0, 0, 4, 1><<<dim3((DPROJ + 127) / 128, SEQ / 128), 256, SM1>>>(
        u16, nullptr, Whi, Wlo, zx, SEQ, DPROJ, DMODEL);
    // fork after GEMM1: dtscan on s2 (independent of conv)
    cudaEventRecord(evA, 0);
    cudaStreamWaitEvent(s2, evA, 0);
    dtscan_kernel<<<NCH * NH, CH, 0, s2>>>(dt_bias, A_log);
    cudaEventRecord(evDt, s2);
    // 2. conv (+C split) on main stream
    conv_silu_kernel<<<dim3((DCONVIN + 255) / 256, SEQ / 8), 256>>>(conv_w, conv_b);
    // fork after conv: gram on s2 (needs conv only; underfilled grid overlaps chunkstate)
    cudaEventRecord(evConv, 0);
    cudaStreamWaitEvent(s2, evConv, 0);
    gram_kernel<<<NCH, 256, 0, s2>>>();
    cudaEventRecord(evGram, s2);
    // 4. chunk-local states (needs conv + dtscan)
    cudaStreamWaitEvent(0, evDt, 0);
    chunkstate_mma_kernel<<<NCH * NH, 256, SMC>>>();
    // 5. inter-chunk scan
    scan_kernel<<<(NH * HD * (DSTATE / 2)) / 256, 256>>>();
    // 5b. inter term (batched TC)
    gemm_bf16s_kernel<1, 1, 3><<<dim3(DINNER / 128, 1, NCH), 256, SM2>>>(
        Chi, Clo, Hhi, Hlo, Inter, CH, DINNER, DSTATE);
    // 6. per-chunk output (needs gram)
    cudaStreamWaitEvent(0, evGram, 0);
    chunkout_mma_kernel<<<NCH * NH, 256, SMO>>>(Dv);
    // 7. RMSNorm + gate
    normgate_kernel<<<SEQ, 256>>>(norm_w, norm_b);
    // 8. out_proj GEMM (needs W_out conversion)
    cudaStreamWaitEvent(0, evV, 0);
    gemm_bf16s_kernel<1, 0, 3><<<dim3(DMODEL / 128, SEQ / 128), 256, SM2>>>(
        Ghi, Glo, Vhi, Vlo, out, SEQ, DMODEL, DINNER);
}